// round 8
// baseline (speedup 1.0000x reference)
#include <cuda_runtime.h>
#include <cuda_bf16.h>
#include <math.h>
#include <stdint.h>

// MultiHeadAttention: B=4, S=2048, E=1024, H=16, D=64
// Outputs: out [B,S,E] fp32, attention_weights [B,H,S,S] fp32.
//
// R8: norm_pv converted to mma.sync bf16 3-term split (PV on tensor pipe).
// Projections (R6) and scores (R7) unchanged.

#define BB   4
#define SS   2048
#define EE   1024
#define HH   16
#define DD   64
#define MTOT (BB*SS)          // 8192
#define BH   (BB*HH)          // 64

__device__ float g_q[MTOT*EE];
__device__ float g_k[MTOT*EE];
__device__ float g_v[MTOT*EE];
__device__ float g_ctx[MTOT*EE];
__device__ float g_m[BH*SS];
__device__ float g_s[BH*SS];

// ===========================================================================
// bf16 hi/lo split helpers + warp mma
// ===========================================================================
__device__ __forceinline__ void f32x2_hilo(float x, float y, uint32_t& hi, uint32_t& lo) {
    __nv_bfloat162 h, l;
    h.x = __float2bfloat16(x); l.x = __float2bfloat16(x - __bfloat162float(h.x));
    h.y = __float2bfloat16(y); l.y = __float2bfloat16(y - __bfloat162float(h.y));
    hi = *(uint32_t*)&h; lo = *(uint32_t*)&l;
}

__device__ __forceinline__ void mma_bf16(float* d,
    uint32_t a0, uint32_t a1, uint32_t a2, uint32_t a3, uint32_t b0, uint32_t b1)
{
    asm volatile(
        "mma.sync.aligned.m16n8k16.row.col.f32.bf16.bf16.f32 "
        "{%0,%1,%2,%3}, {%4,%5,%6,%7}, {%8,%9}, {%0,%1,%2,%3};"
        : "+f"(d[0]), "+f"(d[1]), "+f"(d[2]), "+f"(d[3])
        : "r"(a0), "r"(a1), "r"(a2), "r"(a3), "r"(b0), "r"(b1));
}

#define TPAD   72                       // bf16 elems per smem row (64 + 8 pad)
#define TROWB  (TPAD*2)                 // 144 bytes

// ===========================================================================
// Tensor-core projection GEMM (unchanged from R6 pass): C = A @ W^T + bias.
// ===========================================================================
#define OFF_AHI 0
#define OFF_ALO (128*TROWB)             // 18432
#define OFF_BHI (2*128*TROWB)           // 36864
#define OFF_BLO (3*128*TROWB)           // 55296
#define GEMM_SMEM (4*128*TROWB)         // 73728

__global__ __launch_bounds__(256, 1) void gemm_mma_kernel(
    const float* __restrict__ A_ext, int a_sel,
    const float* __restrict__ W, const float* __restrict__ bias,
    float* __restrict__ C_ext, int c_sel)
{
    extern __shared__ __align__(16) char smem[];

    const float* __restrict__ A = (a_sel == 0) ? A_ext : g_ctx;
    float* __restrict__ C;
    switch (c_sel) {
        case 0:  C = g_q;   break;
        case 1:  C = g_k;   break;
        case 2:  C = g_v;   break;
        default: C = C_ext; break;
    }

    const int tid  = threadIdx.x;
    const int wid  = tid >> 5;
    const int lane = tid & 31;
    const int g    = lane >> 2;
    const int tig  = lane & 3;
    const int warpM = wid & 3;
    const int warpN = wid >> 2;
    const int rowBase = blockIdx.y * 128;
    const int colBase = blockIdx.x * 128;

    float acc[2][8][4];
#pragma unroll
    for (int mt = 0; mt < 2; mt++)
#pragma unroll
        for (int nt = 0; nt < 8; nt++)
#pragma unroll
            for (int f = 0; f < 4; f++) acc[mt][nt][f] = 0.f;

    for (int kc = 0; kc < 16; kc++) {
        const int k0g = kc * 64;
#pragma unroll
        for (int l = 0; l < 16; l++) {
            int id   = tid + l * 256;
            int slot = id & 2047;
            int r    = slot >> 4;
            int c4   = (slot & 15) << 2;
            uint32_t so = (uint32_t)(r * TROWB + c4 * 2);
            if (id < 2048) {
                float4 v = *(const float4*)&A[(size_t)(rowBase + r) * EE + k0g + c4];
                uint32_t h0, l0, h1, l1;
                f32x2_hilo(v.x, v.y, h0, l0);
                f32x2_hilo(v.z, v.w, h1, l1);
                *(uint32_t*)(smem + OFF_AHI + so)     = h0;
                *(uint32_t*)(smem + OFF_AHI + so + 4) = h1;
                *(uint32_t*)(smem + OFF_ALO + so)     = l0;
                *(uint32_t*)(smem + OFF_ALO + so + 4) = l1;
            } else {
                float4 v = *(const float4*)&W[(size_t)(colBase + r) * EE + k0g + c4];
                uint32_t h0, l0, h1, l1;
                f32x2_hilo(v.x, v.y, h0, l0);
                f32x2_hilo(v.z, v.w, h1, l1);
                *(uint32_t*)(smem + OFF_BHI + so)     = h0;
                *(uint32_t*)(smem + OFF_BHI + so + 4) = h1;
                *(uint32_t*)(smem + OFF_BLO + so)     = l0;
                *(uint32_t*)(smem + OFF_BLO + so + 4) = l1;
            }
        }
        __syncthreads();

#pragma unroll
        for (int ks = 0; ks < 4; ks++) {
            const int k0 = ks * 16 + tig * 2;
            uint32_t ah[2][4], al[2][4];
#pragma unroll
            for (int mt = 0; mt < 2; mt++) {
                int r0 = warpM * 32 + mt * 16 + g;
                uint32_t o00 = (uint32_t)(r0 * TROWB + k0 * 2);
                uint32_t o10 = o00 + 8 * TROWB;
                ah[mt][0] = *(const uint32_t*)(smem + OFF_AHI + o00);
                ah[mt][1] = *(const uint32_t*)(smem + OFF_AHI + o10);
                ah[mt][2] = *(const uint32_t*)(smem + OFF_AHI + o00 + 16);
                ah[mt][3] = *(const uint32_t*)(smem + OFF_AHI + o10 + 16);
                al[mt][0] = *(const uint32_t*)(smem + OFF_ALO + o00);
                al[mt][1] = *(const uint32_t*)(smem + OFF_ALO + o10);
                al[mt][2] = *(const uint32_t*)(smem + OFF_ALO + o00 + 16);
                al[mt][3] = *(const uint32_t*)(smem + OFF_ALO + o10 + 16);
            }
#pragma unroll
            for (int nt = 0; nt < 8; nt++) {
                int c0 = warpN * 64 + nt * 8 + g;
                uint32_t ob = (uint32_t)(c0 * TROWB + k0 * 2);
                uint32_t bh0 = *(const uint32_t*)(smem + OFF_BHI + ob);
                uint32_t bh1 = *(const uint32_t*)(smem + OFF_BHI + ob + 16);
                uint32_t bl0 = *(const uint32_t*)(smem + OFF_BLO + ob);
                uint32_t bl1 = *(const uint32_t*)(smem + OFF_BLO + ob + 16);
#pragma unroll
                for (int mt = 0; mt < 2; mt++) {
                    mma_bf16(acc[mt][nt], ah[mt][0], ah[mt][1], ah[mt][2], ah[mt][3], bh0, bh1);
                    mma_bf16(acc[mt][nt], ah[mt][0], ah[mt][1], ah[mt][2], ah[mt][3], bl0, bl1);
                    mma_bf16(acc[mt][nt], al[mt][0], al[mt][1], al[mt][2], al[mt][3], bh0, bh1);
                }
            }
        }
        __syncthreads();
    }

#pragma unroll
    for (int nt = 0; nt < 8; nt++) {
        int col = colBase + warpN * 64 + nt * 8 + tig * 2;
        float b0 = bias[col], b1 = bias[col + 1];
#pragma unroll
        for (int mt = 0; mt < 2; mt++) {
            int row0 = rowBase + warpM * 32 + mt * 16 + g;
            float2 v0 = make_float2(acc[mt][nt][0] + b0, acc[mt][nt][1] + b1);
            float2 v1 = make_float2(acc[mt][nt][2] + b0, acc[mt][nt][3] + b1);
            *(float2*)&C[(size_t)row0 * EE + col]       = v0;
            *(float2*)&C[(size_t)(row0 + 8) * EE + col] = v1;
        }
    }
}

// ===========================================================================
// scores + online row stats via mma.sync (unchanged from R7 pass @586us)
// ===========================================================================
#define SC_QHI 0
#define SC_QLO (128*TROWB)
#define SC_KHI (2*128*TROWB)
#define SC_KLO (3*128*TROWB)
#define SC_SMEM (4*128*TROWB)           // 73728

__global__ __launch_bounds__(256, 1) void scores_mma_kernel(float* __restrict__ attn)
{
    extern __shared__ __align__(16) char smem[];
    __shared__ float sm_m[2][128];
    __shared__ float sm_s[2][128];

    const int bh = blockIdx.y;
    const int b  = bh >> 4;
    const int h  = bh & 15;
    const int rowBase = blockIdx.x * 128;
    const float* __restrict__ Qp = g_q + (size_t)b * SS * EE + h * DD;
    const float* __restrict__ Kp = g_k + (size_t)b * SS * EE + h * DD;
    float* __restrict__ Cb = attn + (size_t)bh * SS * SS;

    const int tid  = threadIdx.x;
    const int wid  = tid >> 5;
    const int lane = tid & 31;
    const int g    = lane >> 2;
    const int tig  = lane & 3;
    const int warpM = wid & 3;
    const int warpN = wid >> 2;

#pragma unroll
    for (int l = 0; l < 8; l++) {
        int id = tid + l * 256;
        int r  = id >> 4;
        int c4 = (id & 15) << 2;
        uint32_t so = (uint32_t)(r * TROWB + c4 * 2);
        float4 v = *(const float4*)&Qp[(size_t)(rowBase + r) * EE + c4];
        uint32_t h0, l0, h1, l1;
        f32x2_hilo(v.x, v.y, h0, l0);
        f32x2_hilo(v.z, v.w, h1, l1);
        *(uint32_t*)(smem + SC_QHI + so)     = h0;
        *(uint32_t*)(smem + SC_QHI + so + 4) = h1;
        *(uint32_t*)(smem + SC_QLO + so)     = l0;
        *(uint32_t*)(smem + SC_QLO + so + 4) = l1;
    }

    float m_run[4], s_run[4];
#pragma unroll
    for (int i = 0; i < 4; i++) { m_run[i] = -INFINITY; s_run[i] = 0.f; }

    for (int ct = 0; ct < 16; ct++) {
        const int colBase = ct * 128;
        __syncthreads();
#pragma unroll
        for (int l = 0; l < 8; l++) {
            int id = tid + l * 256;
            int r  = id >> 4;
            int c4 = (id & 15) << 2;
            uint32_t so = (uint32_t)(r * TROWB + c4 * 2);
            float4 v = *(const float4*)&Kp[(size_t)(colBase + r) * EE + c4];
            uint32_t h0, l0, h1, l1;
            f32x2_hilo(v.x, v.y, h0, l0);
            f32x2_hilo(v.z, v.w, h1, l1);
            *(uint32_t*)(smem + SC_KHI + so)     = h0;
            *(uint32_t*)(smem + SC_KHI + so + 4) = h1;
            *(uint32_t*)(smem + SC_KLO + so)     = l0;
            *(uint32_t*)(smem + SC_KLO + so + 4) = l1;
        }
        __syncthreads();

        float acc[2][8][4];
#pragma unroll
        for (int mt = 0; mt < 2; mt++)
#pragma unroll
            for (int nt = 0; nt < 8; nt++)
#pragma unroll
                for (int f = 0; f < 4; f++) acc[mt][nt][f] = 0.f;

#pragma unroll
        for (int ks = 0; ks < 4; ks++) {
            const int k0 = ks * 16 + tig * 2;
            uint32_t ah[2][4], al[2][4];
#pragma unroll
            for (int mt = 0; mt < 2; mt++) {
                int r0 = warpM * 32 + mt * 16 + g;
                uint32_t o00 = (uint32_t)(r0 * TROWB + k0 * 2);
                uint32_t o10 = o00 + 8 * TROWB;
                ah[mt][0] = *(const uint32_t*)(smem + SC_QHI + o00);
                ah[mt][1] = *(const uint32_t*)(smem + SC_QHI + o10);
                ah[mt][2] = *(const uint32_t*)(smem + SC_QHI + o00 + 16);
                ah[mt][3] = *(const uint32_t*)(smem + SC_QHI + o10 + 16);
                al[mt][0] = *(const uint32_t*)(smem + SC_QLO + o00);
                al[mt][1] = *(const uint32_t*)(smem + SC_QLO + o10);
                al[mt][2] = *(const uint32_t*)(smem + SC_QLO + o00 + 16);
                al[mt][3] = *(const uint32_t*)(smem + SC_QLO + o10 + 16);
            }
#pragma unroll
            for (int nt = 0; nt < 8; nt++) {
                int c0 = warpN * 64 + nt * 8 + g;
                uint32_t ob = (uint32_t)(c0 * TROWB + k0 * 2);
                uint32_t bh0 = *(const uint32_t*)(smem + SC_KHI + ob);
                uint32_t bh1 = *(const uint32_t*)(smem + SC_KHI + ob + 16);
                uint32_t bl0 = *(const uint32_t*)(smem + SC_KLO + ob);
                uint32_t bl1 = *(const uint32_t*)(smem + SC_KLO + ob + 16);
#pragma unroll
                for (int mt = 0; mt < 2; mt++) {
                    mma_bf16(acc[mt][nt], ah[mt][0], ah[mt][1], ah[mt][2], ah[mt][3], bh0, bh1);
                    mma_bf16(acc[mt][nt], ah[mt][0], ah[mt][1], ah[mt][2], ah[mt][3], bl0, bl1);
                    mma_bf16(acc[mt][nt], al[mt][0], al[mt][1], al[mt][2], al[mt][3], bh0, bh1);
                }
            }
        }

#pragma unroll
        for (int mt = 0; mt < 2; mt++) {
#pragma unroll
            for (int nt = 0; nt < 8; nt++) {
#pragma unroll
                for (int f = 0; f < 4; f++) acc[mt][nt][f] *= 0.125f;
                int col  = colBase + warpN * 64 + nt * 8 + tig * 2;
                int row0 = rowBase + warpM * 32 + mt * 16 + g;
                *(float2*)&Cb[(size_t)row0 * SS + col] =
                    make_float2(acc[mt][nt][0], acc[mt][nt][1]);
                *(float2*)&Cb[(size_t)(row0 + 8) * SS + col] =
                    make_float2(acc[mt][nt][2], acc[mt][nt][3]);
            }
#pragma unroll
            for (int p = 0; p < 2; p++) {
                int si = mt * 2 + p;
                float rmax = -INFINITY;
#pragma unroll
                for (int nt = 0; nt < 8; nt++) {
                    rmax = fmaxf(rmax, fmaxf(acc[mt][nt][p * 2], acc[mt][nt][p * 2 + 1]));
                }
                rmax = fmaxf(rmax, __shfl_xor_sync(0xffffffffu, rmax, 1));
                rmax = fmaxf(rmax, __shfl_xor_sync(0xffffffffu, rmax, 2));
                float m_new = fmaxf(m_run[si], rmax);
                float psum = 0.f;
#pragma unroll
                for (int nt = 0; nt < 8; nt++) {
                    psum += __expf(acc[mt][nt][p * 2]     - m_new);
                    psum += __expf(acc[mt][nt][p * 2 + 1] - m_new);
                }
                psum += __shfl_xor_sync(0xffffffffu, psum, 1);
                psum += __shfl_xor_sync(0xffffffffu, psum, 2);
                s_run[si] = s_run[si] * __expf(m_run[si] - m_new) + psum;
                m_run[si] = m_new;
            }
        }
    }

    if (tig == 0) {
#pragma unroll
        for (int mt = 0; mt < 2; mt++)
#pragma unroll
            for (int p = 0; p < 2; p++) {
                int r = warpM * 32 + mt * 16 + p * 8 + g;
                sm_m[warpN][r] = m_run[mt * 2 + p];
                sm_s[warpN][r] = s_run[mt * 2 + p];
            }
    }
    __syncthreads();
    if (tid < 128) {
        float m0 = sm_m[0][tid], m1 = sm_m[1][tid];
        float mm = fmaxf(m0, m1);
        float ss = sm_s[0][tid] * __expf(m0 - mm) + sm_s[1][tid] * __expf(m1 - mm);
        g_m[(size_t)bh * SS + rowBase + tid] = mm;
        g_s[(size_t)bh * SS + rowBase + tid] = ss;
    }
}

// ===========================================================================
// R8: normalize + PV via mma.sync bf16 3-term split + feature-dim softmax.
// CTA = 128 rows x 64 d of one (b,h); k = 2048 in 16 chunks of 128.
// 8 warps = 4(M) x 2(N), warp tile 32x32 (mt=2, nt=4).
// Per chunk: P raw->normalized (write attention_weights) + split hi/lo smem;
// V chunk staged transposed [d][k] hi/lo. Epilogue reuses smem as Ct.
// Smem: PHI/PLO 128x272B, VTH/VTL 64x272B = 104448 B dynamic.
// ===========================================================================
#define PROWB  272                       // 136 bf16 per row (128 + 8 pad)
#define NP_PHI 0
#define NP_PLO (128*PROWB)               // 34816
#define NP_VTH (2*128*PROWB)             // 69632
#define NP_VTL (2*128*PROWB + 64*PROWB)  // 87040
#define NP_SMEM (2*128*PROWB + 2*64*PROWB) // 104448

__global__ __launch_bounds__(256, 1) void norm_pv_mma_kernel(float* __restrict__ attn)
{
    extern __shared__ __align__(16) char smem[];
    __shared__ float m_s[128];
    __shared__ float i_s[128];

    const int bh = blockIdx.y;
    const int b  = bh >> 4;
    const int h  = bh & 15;
    const int rowBase = blockIdx.x * 128;
    float* __restrict__ P = attn + (size_t)bh * SS * SS;
    const float* __restrict__ V = g_v + (size_t)b * SS * EE + h * DD;

    const int tid  = threadIdx.x;
    const int wid  = tid >> 5;
    const int lane = tid & 31;
    const int g    = lane >> 2;
    const int tig  = lane & 3;
    const int warpM = wid & 3;
    const int warpN = wid >> 2;

    if (tid < 128) {
        m_s[tid] = g_m[(size_t)bh * SS + rowBase + tid];
        i_s[tid] = 1.f / g_s[(size_t)bh * SS + rowBase + tid];
    }
    __syncthreads();

    float acc[2][4][4];
#pragma unroll
    for (int mt = 0; mt < 2; mt++)
#pragma unroll
        for (int nt = 0; nt < 4; nt++)
#pragma unroll
            for (int f = 0; f < 4; f++) acc[mt][nt][f] = 0.f;

    for (int ck = 0; ck < 16; ck++) {
        const int k0g = ck * 128;
        if (ck) __syncthreads();

        // --- stage P: read raw, normalize, write attention_weights, split ---
#pragma unroll
        for (int l = 0; l < 16; l++) {
            int id = tid + l * 256;          // 0..4095
            int r  = id >> 5;                // 0..127
            int c4 = (id & 31) << 2;         // 0..124
            float* addr = &P[(size_t)(rowBase + r) * SS + k0g + c4];
            float4 pv = *(const float4*)addr;
            float m = m_s[r], inv = i_s[r];
            pv.x = __expf(pv.x - m) * inv;
            pv.y = __expf(pv.y - m) * inv;
            pv.z = __expf(pv.z - m) * inv;
            pv.w = __expf(pv.w - m) * inv;
            *(float4*)addr = pv;             // normalized attention_weights out
            uint32_t h01, l01, h23, l23;
            f32x2_hilo(pv.x, pv.y, h01, l01);
            f32x2_hilo(pv.z, pv.w, h23, l23);
            uint32_t so = (uint32_t)(r * PROWB + c4 * 2);
            *(uint32_t*)(smem + NP_PHI + so)     = h01;
            *(uint32_t*)(smem + NP_PHI + so + 4) = h23;
            *(uint32_t*)(smem + NP_PLO + so)     = l01;
            *(uint32_t*)(smem + NP_PLO + so + 4) = l23;
        }

        // --- stage V chunk transposed: Vt[d][k] hi/lo ---
#pragma unroll
        for (int l = 0; l < 8; l++) {
            int id = tid + l * 256;          // 0..2047
            int r  = id & 127;               // k within chunk
            int c  = (id >> 7) << 2;         // d = 0,4,...,60
            float4 v = *(const float4*)&V[(size_t)(k0g + r) * EE + c];
            float vv[4] = {v.x, v.y, v.z, v.w};
#pragma unroll
            for (int i = 0; i < 4; i++) {
                __nv_bfloat16 vh = __float2bfloat16(vv[i]);
                __nv_bfloat16 vl = __float2bfloat16(vv[i] - __bfloat162float(vh));
                *(__nv_bfloat16*)(smem + NP_VTH + (uint32_t)((c + i) * PROWB + r * 2)) = vh;
                *(__nv_bfloat16*)(smem + NP_VTL + (uint32_t)((c + i) * PROWB + r * 2)) = vl;
            }
        }
        __syncthreads();

        // --- PV mma: 8 k-steps of 16 ---
#pragma unroll
        for (int ks = 0; ks < 8; ks++) {
            const int k0 = ks * 16 + tig * 2;
            uint32_t ah[2][4], al[2][4];
#pragma unroll
            for (int mt = 0; mt < 2; mt++) {
                int r0 = warpM * 32 + mt * 16 + g;
                uint32_t o00 = (uint32_t)(r0 * PROWB + k0 * 2);
                uint32_t o10 = o00 + 8 * PROWB;
                ah[mt][0] = *(const uint32_t*)(smem + NP_PHI + o00);
                ah[mt][1] = *(const uint32_t*)(smem + NP_PHI + o10);
                ah[mt][2] = *(const uint32_t*)(smem + NP_PHI + o00 + 16);
                ah[mt][3] = *(const uint32_t*)(smem + NP_PHI + o10 + 16);
                al[mt][0] = *(const uint32_t*)(smem + NP_PLO + o00);
                al[mt][1] = *(const uint32_t*)(smem + NP_PLO + o10);
                al[mt][2] = *(const uint32_t*)(smem + NP_PLO + o00 + 16);
                al[mt][3] = *(const uint32_t*)(smem + NP_PLO + o10 + 16);
            }
#pragma unroll
            for (int nt = 0; nt < 4; nt++) {
                int c0 = warpN * 32 + nt * 8 + g;
                uint32_t ob = (uint32_t)(c0 * PROWB + k0 * 2);
                uint32_t bh0 = *(const uint32_t*)(smem + NP_VTH + ob);
                uint32_t bh1 = *(const uint32_t*)(smem + NP_VTH + ob + 16);
                uint32_t bl0 = *(const uint32_t*)(smem + NP_VTL + ob);
                uint32_t bl1 = *(const uint32_t*)(smem + NP_VTL + ob + 16);
#pragma unroll
                for (int mt = 0; mt < 2; mt++) {
                    mma_bf16(acc[mt][nt], ah[mt][0], ah[mt][1], ah[mt][2], ah[mt][3], bh0, bh1);
                    mma_bf16(acc[mt][nt], ah[mt][0], ah[mt][1], ah[mt][2], ah[mt][3], bl0, bl1);
                    mma_bf16(acc[mt][nt], al[mt][0], al[mt][1], al[mt][2], al[mt][3], bh0, bh1);
                }
            }
        }
    }
    __syncthreads();

    // --- epilogue: accs -> Ct (reuse staging smem), feature-dim softmax ---
    float* Ct = (float*)smem;               // [128][68]
#pragma unroll
    for (int mt = 0; mt < 2; mt++)
#pragma unroll
        for (int nt = 0; nt < 4; nt++) {
            int r0 = warpM * 32 + mt * 16 + g;
            int c0 = warpN * 32 + nt * 8 + tig * 2;
            Ct[r0 * 68 + c0]           = acc[mt][nt][0];
            Ct[r0 * 68 + c0 + 1]       = acc[mt][nt][1];
            Ct[(r0 + 8) * 68 + c0]     = acc[mt][nt][2];
            Ct[(r0 + 8) * 68 + c0 + 1] = acc[mt][nt][3];
        }
    __syncthreads();

    if (tid < 128) {
        const int r = tid;
        float* rp = Ct + r * 68;
        float m = rp[0];
#pragma unroll
        for (int d = 1; d < DD; d++) m = fmaxf(m, rp[d]);
        float s = 0.f;
#pragma unroll
        for (int d = 0; d < DD; d++) { float e = __expf(rp[d] - m); rp[d] = e; s += e; }
        float inv = 1.f / s;
        float* __restrict__ dst = g_ctx + ((size_t)b * SS + rowBase + r) * EE + h * DD;
#pragma unroll
        for (int d = 0; d < DD; d++) dst[d] = rp[d] * inv;
    }
}

// ---------------------------------------------------------------------------
extern "C" void kernel_launch(void* const* d_in, const int* in_sizes, int n_in,
                              void* d_out, int out_size)
{
    const float* key   = (const float*)d_in[0];
    const float* query = (const float*)d_in[1];
    const float* value = (const float*)d_in[2];
    const float* wk_w  = (const float*)d_in[3];
    const float* wk_b  = (const float*)d_in[4];
    const float* wq_w  = (const float*)d_in[5];
    const float* wq_b  = (const float*)d_in[6];
    const float* wv_w  = (const float*)d_in[7];
    const float* wv_b  = (const float*)d_in[8];
    const float* out_w = (const float*)d_in[9];
    const float* out_b = (const float*)d_in[10];

    float* out  = (float*)d_out;                       // [B,S,E]
    float* attn = out + (size_t)MTOT * EE;             // [B,H,S,S]

    static int smem_set = 0;
    if (!smem_set) {
        cudaFuncSetAttribute(gemm_mma_kernel,
                             cudaFuncAttributeMaxDynamicSharedMemorySize, GEMM_SMEM);
        cudaFuncSetAttribute(scores_mma_kernel,
                             cudaFuncAttributeMaxDynamicSharedMemorySize, SC_SMEM);
        cudaFuncSetAttribute(norm_pv_mma_kernel,
                             cudaFuncAttributeMaxDynamicSharedMemorySize, NP_SMEM);
        smem_set = 1;
    }

    dim3 gProj(EE / 128, MTOT / 128);                  // (8, 64)
    gemm_mma_kernel<<<gProj, 256, GEMM_SMEM>>>(query, 0, wq_w, wq_b, nullptr, 0);
    gemm_mma_kernel<<<gProj, 256, GEMM_SMEM>>>(key,   0, wk_w, wk_b, nullptr, 1);
    gemm_mma_kernel<<<gProj, 256, GEMM_SMEM>>>(value, 0, wv_w, wv_b, nullptr, 2);

    dim3 gScores(SS / 128, BH);                        // (16, 64)
    scores_mma_kernel<<<gScores, 256, SC_SMEM>>>(attn);

    dim3 gPV(SS / 128, BH);                            // (16, 64)
    norm_pv_mma_kernel<<<gPV, 256, NP_SMEM>>>(attn);

    gemm_mma_kernel<<<gProj, 256, GEMM_SMEM>>>(nullptr, 1, out_w, out_b, out, 3);
}

// round 9
// speedup vs baseline: 1.2346x; 1.2346x over previous
#include <cuda_runtime.h>
#include <cuda_bf16.h>
#include <math.h>
#include <stdint.h>

// MultiHeadAttention: B=4, S=2048, E=1024, H=16, D=64
// Outputs: out [B,S,E] fp32, attention_weights [B,H,S,S] fp32.
//
// R9: (a) revert norm_pv to the proven fp32 kernel (R8 mma version regressed:
// traffic/staging bound, not FFMA bound); (b) software-pipeline global->smem
// staging in gemm_mma and scores_mma (register prefetch of next K-chunk
// overlaps DRAM latency with tensor-pipe work).

#define BB   4
#define SS   2048
#define EE   1024
#define HH   16
#define DD   64
#define MTOT (BB*SS)          // 8192
#define BH   (BB*HH)          // 64

__device__ float g_q[MTOT*EE];
__device__ float g_k[MTOT*EE];
__device__ float g_v[MTOT*EE];
__device__ float g_ctx[MTOT*EE];
__device__ float g_m[BH*SS];
__device__ float g_s[BH*SS];

// ===========================================================================
// bf16 hi/lo split helpers + warp mma
// ===========================================================================
__device__ __forceinline__ void f32x2_hilo(float x, float y, uint32_t& hi, uint32_t& lo) {
    __nv_bfloat162 h, l;
    h.x = __float2bfloat16(x); l.x = __float2bfloat16(x - __bfloat162float(h.x));
    h.y = __float2bfloat16(y); l.y = __float2bfloat16(y - __bfloat162float(h.y));
    hi = *(uint32_t*)&h; lo = *(uint32_t*)&l;
}

__device__ __forceinline__ void mma_bf16(float* d,
    uint32_t a0, uint32_t a1, uint32_t a2, uint32_t a3, uint32_t b0, uint32_t b1)
{
    asm volatile(
        "mma.sync.aligned.m16n8k16.row.col.f32.bf16.bf16.f32 "
        "{%0,%1,%2,%3}, {%4,%5,%6,%7}, {%8,%9}, {%0,%1,%2,%3};"
        : "+f"(d[0]), "+f"(d[1]), "+f"(d[2]), "+f"(d[3])
        : "r"(a0), "r"(a1), "r"(a2), "r"(a3), "r"(b0), "r"(b1));
}

#define TPAD   72                       // bf16 elems per smem row (64 + 8 pad)
#define TROWB  (TPAD*2)                 // 144 bytes

// ===========================================================================
// Tensor-core projection GEMM with pipelined staging: C = A @ W^T + bias.
// CTA 128x128, K chunks of 64. Next chunk prefetched into regs during mma.
// ===========================================================================
#define OFF_AHI 0
#define OFF_ALO (128*TROWB)             // 18432
#define OFF_BHI (2*128*TROWB)           // 36864
#define OFF_BLO (3*128*TROWB)           // 55296
#define GEMM_SMEM (4*128*TROWB)         // 73728

__global__ __launch_bounds__(256, 1) void gemm_mma_kernel(
    const float* __restrict__ A_ext, int a_sel,
    const float* __restrict__ W, const float* __restrict__ bias,
    float* __restrict__ C_ext, int c_sel)
{
    extern __shared__ __align__(16) char smem[];

    const float* __restrict__ A = (a_sel == 0) ? A_ext : g_ctx;
    float* __restrict__ C;
    switch (c_sel) {
        case 0:  C = g_q;   break;
        case 1:  C = g_k;   break;
        case 2:  C = g_v;   break;
        default: C = C_ext; break;
    }

    const int tid  = threadIdx.x;
    const int wid  = tid >> 5;
    const int lane = tid & 31;
    const int g    = lane >> 2;
    const int tig  = lane & 3;
    const int warpM = wid & 3;
    const int warpN = wid >> 2;
    const int rowBase = blockIdx.y * 128;
    const int colBase = blockIdx.x * 128;

    // per-thread staging coords (fixed across chunks)
    const int sr = tid >> 4;             // wrong granularity fix below
    (void)sr;

    float acc[2][8][4];
#pragma unroll
    for (int mt = 0; mt < 2; mt++)
#pragma unroll
        for (int nt = 0; nt < 8; nt++)
#pragma unroll
            for (int f = 0; f < 4; f++) acc[mt][nt][f] = 0.f;

    float4 pfa[8], pfb[8];
    // prefetch chunk 0
#pragma unroll
    for (int l = 0; l < 8; l++) {
        int slot = tid + l * 256;        // 0..2047
        int r  = slot >> 4;              // 0..127
        int c4 = (slot & 15) << 2;       // 0..60
        pfa[l] = *(const float4*)&A[(size_t)(rowBase + r) * EE + c4];
        pfb[l] = *(const float4*)&W[(size_t)(colBase + r) * EE + c4];
    }

    for (int kc = 0; kc < 16; kc++) {
        // --- store staged regs to smem as bf16 hi/lo ---
#pragma unroll
        for (int l = 0; l < 8; l++) {
            int slot = tid + l * 256;
            int r  = slot >> 4;
            int c4 = (slot & 15) << 2;
            uint32_t so = (uint32_t)(r * TROWB + c4 * 2);
            uint32_t h0, l0, h1, l1;
            f32x2_hilo(pfa[l].x, pfa[l].y, h0, l0);
            f32x2_hilo(pfa[l].z, pfa[l].w, h1, l1);
            *(uint32_t*)(smem + OFF_AHI + so)     = h0;
            *(uint32_t*)(smem + OFF_AHI + so + 4) = h1;
            *(uint32_t*)(smem + OFF_ALO + so)     = l0;
            *(uint32_t*)(smem + OFF_ALO + so + 4) = l1;
            f32x2_hilo(pfb[l].x, pfb[l].y, h0, l0);
            f32x2_hilo(pfb[l].z, pfb[l].w, h1, l1);
            *(uint32_t*)(smem + OFF_BHI + so)     = h0;
            *(uint32_t*)(smem + OFF_BHI + so + 4) = h1;
            *(uint32_t*)(smem + OFF_BLO + so)     = l0;
            *(uint32_t*)(smem + OFF_BLO + so + 4) = l1;
        }
        __syncthreads();

        // --- prefetch next chunk (overlaps with mma below) ---
        if (kc < 15) {
            const int k0g = (kc + 1) * 64;
#pragma unroll
            for (int l = 0; l < 8; l++) {
                int slot = tid + l * 256;
                int r  = slot >> 4;
                int c4 = (slot & 15) << 2;
                pfa[l] = *(const float4*)&A[(size_t)(rowBase + r) * EE + k0g + c4];
                pfb[l] = *(const float4*)&W[(size_t)(colBase + r) * EE + k0g + c4];
            }
        }

        // --- compute: 4 k-steps of 16 ---
#pragma unroll
        for (int ks = 0; ks < 4; ks++) {
            const int k0 = ks * 16 + tig * 2;
            uint32_t ah[2][4], al[2][4];
#pragma unroll
            for (int mt = 0; mt < 2; mt++) {
                int r0 = warpM * 32 + mt * 16 + g;
                uint32_t o00 = (uint32_t)(r0 * TROWB + k0 * 2);
                uint32_t o10 = o00 + 8 * TROWB;
                ah[mt][0] = *(const uint32_t*)(smem + OFF_AHI + o00);
                ah[mt][1] = *(const uint32_t*)(smem + OFF_AHI + o10);
                ah[mt][2] = *(const uint32_t*)(smem + OFF_AHI + o00 + 16);
                ah[mt][3] = *(const uint32_t*)(smem + OFF_AHI + o10 + 16);
                al[mt][0] = *(const uint32_t*)(smem + OFF_ALO + o00);
                al[mt][1] = *(const uint32_t*)(smem + OFF_ALO + o10);
                al[mt][2] = *(const uint32_t*)(smem + OFF_ALO + o00 + 16);
                al[mt][3] = *(const uint32_t*)(smem + OFF_ALO + o10 + 16);
            }
#pragma unroll
            for (int nt = 0; nt < 8; nt++) {
                int c0 = warpN * 64 + nt * 8 + g;
                uint32_t ob = (uint32_t)(c0 * TROWB + k0 * 2);
                uint32_t bh0 = *(const uint32_t*)(smem + OFF_BHI + ob);
                uint32_t bh1 = *(const uint32_t*)(smem + OFF_BHI + ob + 16);
                uint32_t bl0 = *(const uint32_t*)(smem + OFF_BLO + ob);
                uint32_t bl1 = *(const uint32_t*)(smem + OFF_BLO + ob + 16);
#pragma unroll
                for (int mt = 0; mt < 2; mt++) {
                    mma_bf16(acc[mt][nt], ah[mt][0], ah[mt][1], ah[mt][2], ah[mt][3], bh0, bh1);
                    mma_bf16(acc[mt][nt], ah[mt][0], ah[mt][1], ah[mt][2], ah[mt][3], bl0, bl1);
                    mma_bf16(acc[mt][nt], al[mt][0], al[mt][1], al[mt][2], al[mt][3], bh0, bh1);
                }
            }
        }
        __syncthreads();
    }

#pragma unroll
    for (int nt = 0; nt < 8; nt++) {
        int col = colBase + warpN * 64 + nt * 8 + tig * 2;
        float b0 = bias[col], b1 = bias[col + 1];
#pragma unroll
        for (int mt = 0; mt < 2; mt++) {
            int row0 = rowBase + warpM * 32 + mt * 16 + g;
            float2 v0 = make_float2(acc[mt][nt][0] + b0, acc[mt][nt][1] + b1);
            float2 v1 = make_float2(acc[mt][nt][2] + b0, acc[mt][nt][3] + b1);
            *(float2*)&C[(size_t)row0 * EE + col]       = v0;
            *(float2*)&C[(size_t)(row0 + 8) * EE + col] = v1;
        }
    }
}

// ===========================================================================
// scores + online row stats via mma.sync, pipelined K staging.
// ===========================================================================
#define SC_QHI 0
#define SC_QLO (128*TROWB)
#define SC_KHI (2*128*TROWB)
#define SC_KLO (3*128*TROWB)
#define SC_SMEM (4*128*TROWB)           // 73728

__global__ __launch_bounds__(256, 1) void scores_mma_kernel(float* __restrict__ attn)
{
    extern __shared__ __align__(16) char smem[];
    __shared__ float sm_m[2][128];
    __shared__ float sm_s[2][128];

    const int bh = blockIdx.y;
    const int b  = bh >> 4;
    const int h  = bh & 15;
    const int rowBase = blockIdx.x * 128;
    const float* __restrict__ Qp = g_q + (size_t)b * SS * EE + h * DD;
    const float* __restrict__ Kp = g_k + (size_t)b * SS * EE + h * DD;
    float* __restrict__ Cb = attn + (size_t)bh * SS * SS;

    const int tid  = threadIdx.x;
    const int wid  = tid >> 5;
    const int lane = tid & 31;
    const int g    = lane >> 2;
    const int tig  = lane & 3;
    const int warpM = wid & 3;
    const int warpN = wid >> 2;

    // --- stage Q tile (128 x 64) as bf16 hi/lo, once ---
#pragma unroll
    for (int l = 0; l < 8; l++) {
        int id = tid + l * 256;
        int r  = id >> 4;
        int c4 = (id & 15) << 2;
        uint32_t so = (uint32_t)(r * TROWB + c4 * 2);
        float4 v = *(const float4*)&Qp[(size_t)(rowBase + r) * EE + c4];
        uint32_t h0, l0, h1, l1;
        f32x2_hilo(v.x, v.y, h0, l0);
        f32x2_hilo(v.z, v.w, h1, l1);
        *(uint32_t*)(smem + SC_QHI + so)     = h0;
        *(uint32_t*)(smem + SC_QHI + so + 4) = h1;
        *(uint32_t*)(smem + SC_QLO + so)     = l0;
        *(uint32_t*)(smem + SC_QLO + so + 4) = l1;
    }

    float m_run[4], s_run[4];
#pragma unroll
    for (int i = 0; i < 4; i++) { m_run[i] = -INFINITY; s_run[i] = 0.f; }

    float4 pfk[8];
    // prefetch K tile 0
#pragma unroll
    for (int l = 0; l < 8; l++) {
        int id = tid + l * 256;
        int r  = id >> 4;
        int c4 = (id & 15) << 2;
        pfk[l] = *(const float4*)&Kp[(size_t)r * EE + c4];
    }

    for (int ct = 0; ct < 16; ct++) {
        const int colBase = ct * 128;
        // --- store staged K to smem hi/lo ---
#pragma unroll
        for (int l = 0; l < 8; l++) {
            int id = tid + l * 256;
            int r  = id >> 4;
            int c4 = (id & 15) << 2;
            uint32_t so = (uint32_t)(r * TROWB + c4 * 2);
            uint32_t h0, l0, h1, l1;
            f32x2_hilo(pfk[l].x, pfk[l].y, h0, l0);
            f32x2_hilo(pfk[l].z, pfk[l].w, h1, l1);
            *(uint32_t*)(smem + SC_KHI + so)     = h0;
            *(uint32_t*)(smem + SC_KHI + so + 4) = h1;
            *(uint32_t*)(smem + SC_KLO + so)     = l0;
            *(uint32_t*)(smem + SC_KLO + so + 4) = l1;
        }
        __syncthreads();

        // --- prefetch next K tile (overlaps mma + epilogue) ---
        if (ct < 15) {
            const int nb = (ct + 1) * 128;
#pragma unroll
            for (int l = 0; l < 8; l++) {
                int id = tid + l * 256;
                int r  = id >> 4;
                int c4 = (id & 15) << 2;
                pfk[l] = *(const float4*)&Kp[(size_t)(nb + r) * EE + c4];
            }
        }

        float acc[2][8][4];
#pragma unroll
        for (int mt = 0; mt < 2; mt++)
#pragma unroll
            for (int nt = 0; nt < 8; nt++)
#pragma unroll
                for (int f = 0; f < 4; f++) acc[mt][nt][f] = 0.f;

#pragma unroll
        for (int ks = 0; ks < 4; ks++) {
            const int k0 = ks * 16 + tig * 2;
            uint32_t ah[2][4], al[2][4];
#pragma unroll
            for (int mt = 0; mt < 2; mt++) {
                int r0 = warpM * 32 + mt * 16 + g;
                uint32_t o00 = (uint32_t)(r0 * TROWB + k0 * 2);
                uint32_t o10 = o00 + 8 * TROWB;
                ah[mt][0] = *(const uint32_t*)(smem + SC_QHI + o00);
                ah[mt][1] = *(const uint32_t*)(smem + SC_QHI + o10);
                ah[mt][2] = *(const uint32_t*)(smem + SC_QHI + o00 + 16);
                ah[mt][3] = *(const uint32_t*)(smem + SC_QHI + o10 + 16);
                al[mt][0] = *(const uint32_t*)(smem + SC_QLO + o00);
                al[mt][1] = *(const uint32_t*)(smem + SC_QLO + o10);
                al[mt][2] = *(const uint32_t*)(smem + SC_QLO + o00 + 16);
                al[mt][3] = *(const uint32_t*)(smem + SC_QLO + o10 + 16);
            }
#pragma unroll
            for (int nt = 0; nt < 8; nt++) {
                int c0 = warpN * 64 + nt * 8 + g;
                uint32_t ob = (uint32_t)(c0 * TROWB + k0 * 2);
                uint32_t bh0 = *(const uint32_t*)(smem + SC_KHI + ob);
                uint32_t bh1 = *(const uint32_t*)(smem + SC_KHI + ob + 16);
                uint32_t bl0 = *(const uint32_t*)(smem + SC_KLO + ob);
                uint32_t bl1 = *(const uint32_t*)(smem + SC_KLO + ob + 16);
#pragma unroll
                for (int mt = 0; mt < 2; mt++) {
                    mma_bf16(acc[mt][nt], ah[mt][0], ah[mt][1], ah[mt][2], ah[mt][3], bh0, bh1);
                    mma_bf16(acc[mt][nt], ah[mt][0], ah[mt][1], ah[mt][2], ah[mt][3], bl0, bl1);
                    mma_bf16(acc[mt][nt], al[mt][0], al[mt][1], al[mt][2], al[mt][3], bh0, bh1);
                }
            }
        }

        // --- scale, write raw scores, update per-half online stats ---
#pragma unroll
        for (int mt = 0; mt < 2; mt++) {
#pragma unroll
            for (int nt = 0; nt < 8; nt++) {
#pragma unroll
                for (int f = 0; f < 4; f++) acc[mt][nt][f] *= 0.125f;
                int col  = colBase + warpN * 64 + nt * 8 + tig * 2;
                int row0 = rowBase + warpM * 32 + mt * 16 + g;
                *(float2*)&Cb[(size_t)row0 * SS + col] =
                    make_float2(acc[mt][nt][0], acc[mt][nt][1]);
                *(float2*)&Cb[(size_t)(row0 + 8) * SS + col] =
                    make_float2(acc[mt][nt][2], acc[mt][nt][3]);
            }
#pragma unroll
            for (int p = 0; p < 2; p++) {
                int si = mt * 2 + p;
                float rmax = -INFINITY;
#pragma unroll
                for (int nt = 0; nt < 8; nt++) {
                    rmax = fmaxf(rmax, fmaxf(acc[mt][nt][p * 2], acc[mt][nt][p * 2 + 1]));
                }
                rmax = fmaxf(rmax, __shfl_xor_sync(0xffffffffu, rmax, 1));
                rmax = fmaxf(rmax, __shfl_xor_sync(0xffffffffu, rmax, 2));
                float m_new = fmaxf(m_run[si], rmax);
                float psum = 0.f;
#pragma unroll
                for (int nt = 0; nt < 8; nt++) {
                    psum += __expf(acc[mt][nt][p * 2]     - m_new);
                    psum += __expf(acc[mt][nt][p * 2 + 1] - m_new);
                }
                psum += __shfl_xor_sync(0xffffffffu, psum, 1);
                psum += __shfl_xor_sync(0xffffffffu, psum, 2);
                s_run[si] = s_run[si] * __expf(m_run[si] - m_new) + psum;
                m_run[si] = m_new;
            }
        }
        __syncthreads();
    }

    if (tig == 0) {
#pragma unroll
        for (int mt = 0; mt < 2; mt++)
#pragma unroll
            for (int p = 0; p < 2; p++) {
                int r = warpM * 32 + mt * 16 + p * 8 + g;
                sm_m[warpN][r] = m_run[mt * 2 + p];
                sm_s[warpN][r] = s_run[mt * 2 + p];
            }
    }
    __syncthreads();
    if (tid < 128) {
        float m0 = sm_m[0][tid], m1 = sm_m[1][tid];
        float mm = fmaxf(m0, m1);
        float ss = sm_s[0][tid] * __expf(m0 - mm) + sm_s[1][tid] * __expf(m1 - mm);
        g_m[(size_t)bh * SS + rowBase + tid] = mm;
        g_s[(size_t)bh * SS + rowBase + tid] = ss;
    }
}

// ===========================================================================
// normalize + PV + feature-dim softmax (fp32 -- reverted to the R7 version)
// ===========================================================================
__global__ __launch_bounds__(256) void norm_pv_kernel(float* __restrict__ attn)
{
    const int bh = blockIdx.y;
    const int b  = bh >> 4;
    const int h  = bh & 15;
    const int rowBase = blockIdx.x * 128;
    float* __restrict__ P = attn + (size_t)bh * SS * SS;
    const float* __restrict__ V = g_v + (size_t)b * SS * EE + h * DD;

    __shared__ __align__(16) float Ps[16][128];
    __shared__ __align__(16) float Vs[16][64];
    __shared__ float Ct[128][65];
    __shared__ float m_s[128];
    __shared__ float i_s[128];

    const int tid = threadIdx.x;
    const int ty = tid >> 4;
    const int tx = tid & 15;

    if (tid < 128) {
        m_s[tid] = g_m[(size_t)bh * SS + rowBase + tid];
        i_s[tid] = 1.f / g_s[(size_t)bh * SS + rowBase + tid];
    }
    __syncthreads();

    float acc[8][4];
#pragma unroll
    for (int i = 0; i < 8; i++)
#pragma unroll
        for (int j = 0; j < 4; j++) acc[i][j] = 0.f;

    for (int k0 = 0; k0 < SS; k0 += 16) {
#pragma unroll
        for (int l = 0; l < 2; l++) {
            int id = tid + l * 256;
            int r  = id >> 2;
            int c4 = (id & 3) << 2;
            float* addr = &P[(size_t)(rowBase + r) * SS + k0 + c4];
            float4 pv = *(const float4*)addr;
            float m = m_s[r], inv = i_s[r];
            pv.x = __expf(pv.x - m) * inv;
            pv.y = __expf(pv.y - m) * inv;
            pv.z = __expf(pv.z - m) * inv;
            pv.w = __expf(pv.w - m) * inv;
            *(float4*)addr = pv;
            Ps[c4 + 0][r] = pv.x; Ps[c4 + 1][r] = pv.y;
            Ps[c4 + 2][r] = pv.z; Ps[c4 + 3][r] = pv.w;
        }
        {
            int r = tid >> 4;
            int c = (tid & 15) << 2;
            *(float4*)&Vs[r][c] = *(const float4*)&V[(size_t)(k0 + r) * EE + c];
        }
        __syncthreads();
#pragma unroll
        for (int kk = 0; kk < 16; kk++) {
            float4 a0 = *(const float4*)&Ps[kk][ty * 8];
            float4 a1 = *(const float4*)&Ps[kk][ty * 8 + 4];
            float4 b0 = *(const float4*)&Vs[kk][tx * 4];
            float a[8] = {a0.x, a0.y, a0.z, a0.w, a1.x, a1.y, a1.z, a1.w};
            float bv[4] = {b0.x, b0.y, b0.z, b0.w};
#pragma unroll
            for (int i = 0; i < 8; i++)
#pragma unroll
                for (int j = 0; j < 4; j++) acc[i][j] += a[i] * bv[j];
        }
        __syncthreads();
    }

#pragma unroll
    for (int i = 0; i < 8; i++)
#pragma unroll
        for (int j = 0; j < 4; j++) Ct[ty * 8 + i][tx * 4 + j] = acc[i][j];
    __syncthreads();

    if (tid < 128) {
        const int r = tid;
        float m = Ct[r][0];
#pragma unroll
        for (int d = 1; d < DD; d++) m = fmaxf(m, Ct[r][d]);
        float s = 0.f;
#pragma unroll
        for (int d = 0; d < DD; d++) { float e = __expf(Ct[r][d] - m); Ct[r][d] = e; s += e; }
        float inv = 1.f / s;
        float* __restrict__ dst = g_ctx + ((size_t)b * SS + rowBase + r) * EE + h * DD;
#pragma unroll
        for (int d = 0; d < DD; d++) dst[d] = Ct[r][d] * inv;
    }
}

// ---------------------------------------------------------------------------
extern "C" void kernel_launch(void* const* d_in, const int* in_sizes, int n_in,
                              void* d_out, int out_size)
{
    const float* key   = (const float*)d_in[0];
    const float* query = (const float*)d_in[1];
    const float* value = (const float*)d_in[2];
    const float* wk_w  = (const float*)d_in[3];
    const float* wk_b  = (const float*)d_in[4];
    const float* wq_w  = (const float*)d_in[5];
    const float* wq_b  = (const float*)d_in[6];
    const float* wv_w  = (const float*)d_in[7];
    const float* wv_b  = (const float*)d_in[8];
    const float* out_w = (const float*)d_in[9];
    const float* out_b = (const float*)d_in[10];

    float* out  = (float*)d_out;                       // [B,S,E]
    float* attn = out + (size_t)MTOT * EE;             // [B,H,S,S]

    static int smem_set = 0;
    if (!smem_set) {
        cudaFuncSetAttribute(gemm_mma_kernel,
                             cudaFuncAttributeMaxDynamicSharedMemorySize, GEMM_SMEM);
        cudaFuncSetAttribute(scores_mma_kernel,
                             cudaFuncAttributeMaxDynamicSharedMemorySize, SC_SMEM);
        smem_set = 1;
    }

    dim3 gProj(EE / 128, MTOT / 128);                  // (8, 64)
    gemm_mma_kernel<<<gProj, 256, GEMM_SMEM>>>(query, 0, wq_w, wq_b, nullptr, 0);
    gemm_mma_kernel<<<gProj, 256, GEMM_SMEM>>>(key,   0, wk_w, wk_b, nullptr, 1);
    gemm_mma_kernel<<<gProj, 256, GEMM_SMEM>>>(value, 0, wv_w, wv_b, nullptr, 2);

    dim3 gScores(SS / 128, BH);                        // (16, 64)
    scores_mma_kernel<<<gScores, 256, SC_SMEM>>>(attn);

    dim3 gPV(SS / 128, BH);                            // (16, 64)
    norm_pv_kernel<<<gPV, 256>>>(attn);

    gemm_mma_kernel<<<gProj, 256, GEMM_SMEM>>>(nullptr, 1, out_w, out_b, out, 3);
}

// round 10
// speedup vs baseline: 1.5850x; 1.2838x over previous
#include <cuda_runtime.h>
#include <cuda_bf16.h>
#include <math.h>
#include <stdint.h>

// MultiHeadAttention: B=4, S=2048, E=1024, H=16, D=64
// Outputs: out [B,S,E] fp32, attention_weights [B,H,S,S] fp32.
//
// R10: PV tensorized properly: V pre-transposed to global bf16 (g_vt) once,
// norm_pv uses mma.sync with P hi/lo (2-term) x V bf16, 46KB smem, register
// prefetch pipelining. Projections + scores unchanged from R9 pass.

#define BB   4
#define SS   2048
#define EE   1024
#define HH   16
#define DD   64
#define MTOT (BB*SS)          // 8192
#define BH   (BB*HH)          // 64

__device__ float g_q[MTOT*EE];
__device__ float g_k[MTOT*EE];
__device__ float g_v[MTOT*EE];
__device__ float g_ctx[MTOT*EE];
__device__ float g_m[BH*SS];
__device__ float g_s[BH*SS];
__device__ __nv_bfloat16 g_vt[(size_t)BH*DD*SS];   // V^T per head: [bh][d][s]

// ===========================================================================
// bf16 hi/lo split helpers + warp mma
// ===========================================================================
__device__ __forceinline__ void f32x2_hilo(float x, float y, uint32_t& hi, uint32_t& lo) {
    __nv_bfloat162 h, l;
    h.x = __float2bfloat16(x); l.x = __float2bfloat16(x - __bfloat162float(h.x));
    h.y = __float2bfloat16(y); l.y = __float2bfloat16(y - __bfloat162float(h.y));
    hi = *(uint32_t*)&h; lo = *(uint32_t*)&l;
}
__device__ __forceinline__ uint32_t f32x2_bf(float x, float y) {
    __nv_bfloat162 h;
    h.x = __float2bfloat16(x); h.y = __float2bfloat16(y);
    return *(uint32_t*)&h;
}

__device__ __forceinline__ void mma_bf16(float* d,
    uint32_t a0, uint32_t a1, uint32_t a2, uint32_t a3, uint32_t b0, uint32_t b1)
{
    asm volatile(
        "mma.sync.aligned.m16n8k16.row.col.f32.bf16.bf16.f32 "
        "{%0,%1,%2,%3}, {%4,%5,%6,%7}, {%8,%9}, {%0,%1,%2,%3};"
        : "+f"(d[0]), "+f"(d[1]), "+f"(d[2]), "+f"(d[3])
        : "r"(a0), "r"(a1), "r"(a2), "r"(a3), "r"(b0), "r"(b1));
}

#define TPAD   72                       // bf16 elems per smem row (64 + 8 pad)
#define TROWB  (TPAD*2)                 // 144 bytes

// ===========================================================================
// Tensor-core projection GEMM with pipelined staging (R9, unchanged).
// ===========================================================================
#define OFF_AHI 0
#define OFF_ALO (128*TROWB)
#define OFF_BHI (2*128*TROWB)
#define OFF_BLO (3*128*TROWB)
#define GEMM_SMEM (4*128*TROWB)         // 73728

__global__ __launch_bounds__(256, 1) void gemm_mma_kernel(
    const float* __restrict__ A_ext, int a_sel,
    const float* __restrict__ W, const float* __restrict__ bias,
    float* __restrict__ C_ext, int c_sel)
{
    extern __shared__ __align__(16) char smem[];

    const float* __restrict__ A = (a_sel == 0) ? A_ext : g_ctx;
    float* __restrict__ C;
    switch (c_sel) {
        case 0:  C = g_q;   break;
        case 1:  C = g_k;   break;
        case 2:  C = g_v;   break;
        default: C = C_ext; break;
    }

    const int tid  = threadIdx.x;
    const int wid  = tid >> 5;
    const int lane = tid & 31;
    const int g    = lane >> 2;
    const int tig  = lane & 3;
    const int warpM = wid & 3;
    const int warpN = wid >> 2;
    const int rowBase = blockIdx.y * 128;
    const int colBase = blockIdx.x * 128;

    float acc[2][8][4];
#pragma unroll
    for (int mt = 0; mt < 2; mt++)
#pragma unroll
        for (int nt = 0; nt < 8; nt++)
#pragma unroll
            for (int f = 0; f < 4; f++) acc[mt][nt][f] = 0.f;

    float4 pfa[8], pfb[8];
#pragma unroll
    for (int l = 0; l < 8; l++) {
        int slot = tid + l * 256;
        int r  = slot >> 4;
        int c4 = (slot & 15) << 2;
        pfa[l] = *(const float4*)&A[(size_t)(rowBase + r) * EE + c4];
        pfb[l] = *(const float4*)&W[(size_t)(colBase + r) * EE + c4];
    }

    for (int kc = 0; kc < 16; kc++) {
#pragma unroll
        for (int l = 0; l < 8; l++) {
            int slot = tid + l * 256;
            int r  = slot >> 4;
            int c4 = (slot & 15) << 2;
            uint32_t so = (uint32_t)(r * TROWB + c4 * 2);
            uint32_t h0, l0, h1, l1;
            f32x2_hilo(pfa[l].x, pfa[l].y, h0, l0);
            f32x2_hilo(pfa[l].z, pfa[l].w, h1, l1);
            *(uint32_t*)(smem + OFF_AHI + so)     = h0;
            *(uint32_t*)(smem + OFF_AHI + so + 4) = h1;
            *(uint32_t*)(smem + OFF_ALO + so)     = l0;
            *(uint32_t*)(smem + OFF_ALO + so + 4) = l1;
            f32x2_hilo(pfb[l].x, pfb[l].y, h0, l0);
            f32x2_hilo(pfb[l].z, pfb[l].w, h1, l1);
            *(uint32_t*)(smem + OFF_BHI + so)     = h0;
            *(uint32_t*)(smem + OFF_BHI + so + 4) = h1;
            *(uint32_t*)(smem + OFF_BLO + so)     = l0;
            *(uint32_t*)(smem + OFF_BLO + so + 4) = l1;
        }
        __syncthreads();

        if (kc < 15) {
            const int k0g = (kc + 1) * 64;
#pragma unroll
            for (int l = 0; l < 8; l++) {
                int slot = tid + l * 256;
                int r  = slot >> 4;
                int c4 = (slot & 15) << 2;
                pfa[l] = *(const float4*)&A[(size_t)(rowBase + r) * EE + k0g + c4];
                pfb[l] = *(const float4*)&W[(size_t)(colBase + r) * EE + k0g + c4];
            }
        }

#pragma unroll
        for (int ks = 0; ks < 4; ks++) {
            const int k0 = ks * 16 + tig * 2;
            uint32_t ah[2][4], al[2][4];
#pragma unroll
            for (int mt = 0; mt < 2; mt++) {
                int r0 = warpM * 32 + mt * 16 + g;
                uint32_t o00 = (uint32_t)(r0 * TROWB + k0 * 2);
                uint32_t o10 = o00 + 8 * TROWB;
                ah[mt][0] = *(const uint32_t*)(smem + OFF_AHI + o00);
                ah[mt][1] = *(const uint32_t*)(smem + OFF_AHI + o10);
                ah[mt][2] = *(const uint32_t*)(smem + OFF_AHI + o00 + 16);
                ah[mt][3] = *(const uint32_t*)(smem + OFF_AHI + o10 + 16);
                al[mt][0] = *(const uint32_t*)(smem + OFF_ALO + o00);
                al[mt][1] = *(const uint32_t*)(smem + OFF_ALO + o10);
                al[mt][2] = *(const uint32_t*)(smem + OFF_ALO + o00 + 16);
                al[mt][3] = *(const uint32_t*)(smem + OFF_ALO + o10 + 16);
            }
#pragma unroll
            for (int nt = 0; nt < 8; nt++) {
                int c0 = warpN * 64 + nt * 8 + g;
                uint32_t ob = (uint32_t)(c0 * TROWB + k0 * 2);
                uint32_t bh0 = *(const uint32_t*)(smem + OFF_BHI + ob);
                uint32_t bh1 = *(const uint32_t*)(smem + OFF_BHI + ob + 16);
                uint32_t bl0 = *(const uint32_t*)(smem + OFF_BLO + ob);
                uint32_t bl1 = *(const uint32_t*)(smem + OFF_BLO + ob + 16);
#pragma unroll
                for (int mt = 0; mt < 2; mt++) {
                    mma_bf16(acc[mt][nt], ah[mt][0], ah[mt][1], ah[mt][2], ah[mt][3], bh0, bh1);
                    mma_bf16(acc[mt][nt], ah[mt][0], ah[mt][1], ah[mt][2], ah[mt][3], bl0, bl1);
                    mma_bf16(acc[mt][nt], al[mt][0], al[mt][1], al[mt][2], al[mt][3], bh0, bh1);
                }
            }
        }
        __syncthreads();
    }

#pragma unroll
    for (int nt = 0; nt < 8; nt++) {
        int col = colBase + warpN * 64 + nt * 8 + tig * 2;
        float b0 = bias[col], b1 = bias[col + 1];
#pragma unroll
        for (int mt = 0; mt < 2; mt++) {
            int row0 = rowBase + warpM * 32 + mt * 16 + g;
            float2 v0 = make_float2(acc[mt][nt][0] + b0, acc[mt][nt][1] + b1);
            float2 v1 = make_float2(acc[mt][nt][2] + b0, acc[mt][nt][3] + b1);
            *(float2*)&C[(size_t)row0 * EE + col]       = v0;
            *(float2*)&C[(size_t)(row0 + 8) * EE + col] = v1;
        }
    }
}

// ===========================================================================
// scores + online row stats via mma.sync, pipelined (R9, unchanged).
// ===========================================================================
#define SC_QHI 0
#define SC_QLO (128*TROWB)
#define SC_KHI (2*128*TROWB)
#define SC_KLO (3*128*TROWB)
#define SC_SMEM (4*128*TROWB)           // 73728

__global__ __launch_bounds__(256, 1) void scores_mma_kernel(float* __restrict__ attn)
{
    extern __shared__ __align__(16) char smem[];
    __shared__ float sm_m[2][128];
    __shared__ float sm_s[2][128];

    const int bh = blockIdx.y;
    const int b  = bh >> 4;
    const int h  = bh & 15;
    const int rowBase = blockIdx.x * 128;
    const float* __restrict__ Qp = g_q + (size_t)b * SS * EE + h * DD;
    const float* __restrict__ Kp = g_k + (size_t)b * SS * EE + h * DD;
    float* __restrict__ Cb = attn + (size_t)bh * SS * SS;

    const int tid  = threadIdx.x;
    const int wid  = tid >> 5;
    const int lane = tid & 31;
    const int g    = lane >> 2;
    const int tig  = lane & 3;
    const int warpM = wid & 3;
    const int warpN = wid >> 2;

#pragma unroll
    for (int l = 0; l < 8; l++) {
        int id = tid + l * 256;
        int r  = id >> 4;
        int c4 = (id & 15) << 2;
        uint32_t so = (uint32_t)(r * TROWB + c4 * 2);
        float4 v = *(const float4*)&Qp[(size_t)(rowBase + r) * EE + c4];
        uint32_t h0, l0, h1, l1;
        f32x2_hilo(v.x, v.y, h0, l0);
        f32x2_hilo(v.z, v.w, h1, l1);
        *(uint32_t*)(smem + SC_QHI + so)     = h0;
        *(uint32_t*)(smem + SC_QHI + so + 4) = h1;
        *(uint32_t*)(smem + SC_QLO + so)     = l0;
        *(uint32_t*)(smem + SC_QLO + so + 4) = l1;
    }

    float m_run[4], s_run[4];
#pragma unroll
    for (int i = 0; i < 4; i++) { m_run[i] = -INFINITY; s_run[i] = 0.f; }

    float4 pfk[8];
#pragma unroll
    for (int l = 0; l < 8; l++) {
        int id = tid + l * 256;
        int r  = id >> 4;
        int c4 = (id & 15) << 2;
        pfk[l] = *(const float4*)&Kp[(size_t)r * EE + c4];
    }

    for (int ct = 0; ct < 16; ct++) {
        const int colBase = ct * 128;
#pragma unroll
        for (int l = 0; l < 8; l++) {
            int id = tid + l * 256;
            int r  = id >> 4;
            int c4 = (id & 15) << 2;
            uint32_t so = (uint32_t)(r * TROWB + c4 * 2);
            uint32_t h0, l0, h1, l1;
            f32x2_hilo(pfk[l].x, pfk[l].y, h0, l0);
            f32x2_hilo(pfk[l].z, pfk[l].w, h1, l1);
            *(uint32_t*)(smem + SC_KHI + so)     = h0;
            *(uint32_t*)(smem + SC_KHI + so + 4) = h1;
            *(uint32_t*)(smem + SC_KLO + so)     = l0;
            *(uint32_t*)(smem + SC_KLO + so + 4) = l1;
        }
        __syncthreads();

        if (ct < 15) {
            const int nb = (ct + 1) * 128;
#pragma unroll
            for (int l = 0; l < 8; l++) {
                int id = tid + l * 256;
                int r  = id >> 4;
                int c4 = (id & 15) << 2;
                pfk[l] = *(const float4*)&Kp[(size_t)(nb + r) * EE + c4];
            }
        }

        float acc[2][8][4];
#pragma unroll
        for (int mt = 0; mt < 2; mt++)
#pragma unroll
            for (int nt = 0; nt < 8; nt++)
#pragma unroll
                for (int f = 0; f < 4; f++) acc[mt][nt][f] = 0.f;

#pragma unroll
        for (int ks = 0; ks < 4; ks++) {
            const int k0 = ks * 16 + tig * 2;
            uint32_t ah[2][4], al[2][4];
#pragma unroll
            for (int mt = 0; mt < 2; mt++) {
                int r0 = warpM * 32 + mt * 16 + g;
                uint32_t o00 = (uint32_t)(r0 * TROWB + k0 * 2);
                uint32_t o10 = o00 + 8 * TROWB;
                ah[mt][0] = *(const uint32_t*)(smem + SC_QHI + o00);
                ah[mt][1] = *(const uint32_t*)(smem + SC_QHI + o10);
                ah[mt][2] = *(const uint32_t*)(smem + SC_QHI + o00 + 16);
                ah[mt][3] = *(const uint32_t*)(smem + SC_QHI + o10 + 16);
                al[mt][0] = *(const uint32_t*)(smem + SC_QLO + o00);
                al[mt][1] = *(const uint32_t*)(smem + SC_QLO + o10);
                al[mt][2] = *(const uint32_t*)(smem + SC_QLO + o00 + 16);
                al[mt][3] = *(const uint32_t*)(smem + SC_QLO + o10 + 16);
            }
#pragma unroll
            for (int nt = 0; nt < 8; nt++) {
                int c0 = warpN * 64 + nt * 8 + g;
                uint32_t ob = (uint32_t)(c0 * TROWB + k0 * 2);
                uint32_t bh0 = *(const uint32_t*)(smem + SC_KHI + ob);
                uint32_t bh1 = *(const uint32_t*)(smem + SC_KHI + ob + 16);
                uint32_t bl0 = *(const uint32_t*)(smem + SC_KLO + ob);
                uint32_t bl1 = *(const uint32_t*)(smem + SC_KLO + ob + 16);
#pragma unroll
                for (int mt = 0; mt < 2; mt++) {
                    mma_bf16(acc[mt][nt], ah[mt][0], ah[mt][1], ah[mt][2], ah[mt][3], bh0, bh1);
                    mma_bf16(acc[mt][nt], ah[mt][0], ah[mt][1], ah[mt][2], ah[mt][3], bl0, bl1);
                    mma_bf16(acc[mt][nt], al[mt][0], al[mt][1], al[mt][2], al[mt][3], bh0, bh1);
                }
            }
        }

#pragma unroll
        for (int mt = 0; mt < 2; mt++) {
#pragma unroll
            for (int nt = 0; nt < 8; nt++) {
#pragma unroll
                for (int f = 0; f < 4; f++) acc[mt][nt][f] *= 0.125f;
                int col  = colBase + warpN * 64 + nt * 8 + tig * 2;
                int row0 = rowBase + warpM * 32 + mt * 16 + g;
                *(float2*)&Cb[(size_t)row0 * SS + col] =
                    make_float2(acc[mt][nt][0], acc[mt][nt][1]);
                *(float2*)&Cb[(size_t)(row0 + 8) * SS + col] =
                    make_float2(acc[mt][nt][2], acc[mt][nt][3]);
            }
#pragma unroll
            for (int p = 0; p < 2; p++) {
                int si = mt * 2 + p;
                float rmax = -INFINITY;
#pragma unroll
                for (int nt = 0; nt < 8; nt++) {
                    rmax = fmaxf(rmax, fmaxf(acc[mt][nt][p * 2], acc[mt][nt][p * 2 + 1]));
                }
                rmax = fmaxf(rmax, __shfl_xor_sync(0xffffffffu, rmax, 1));
                rmax = fmaxf(rmax, __shfl_xor_sync(0xffffffffu, rmax, 2));
                float m_new = fmaxf(m_run[si], rmax);
                float psum = 0.f;
#pragma unroll
                for (int nt = 0; nt < 8; nt++) {
                    psum += __expf(acc[mt][nt][p * 2]     - m_new);
                    psum += __expf(acc[mt][nt][p * 2 + 1] - m_new);
                }
                psum += __shfl_xor_sync(0xffffffffu, psum, 1);
                psum += __shfl_xor_sync(0xffffffffu, psum, 2);
                s_run[si] = s_run[si] * __expf(m_run[si] - m_new) + psum;
                m_run[si] = m_new;
            }
        }
        __syncthreads();
    }

    if (tig == 0) {
#pragma unroll
        for (int mt = 0; mt < 2; mt++)
#pragma unroll
            for (int p = 0; p < 2; p++) {
                int r = warpM * 32 + mt * 16 + p * 8 + g;
                sm_m[warpN][r] = m_run[mt * 2 + p];
                sm_s[warpN][r] = s_run[mt * 2 + p];
            }
    }
    __syncthreads();
    if (tid < 128) {
        float m0 = sm_m[0][tid], m1 = sm_m[1][tid];
        float mm = fmaxf(m0, m1);
        float ss = sm_s[0][tid] * __expf(m0 - mm) + sm_s[1][tid] * __expf(m1 - mm);
        g_m[(size_t)bh * SS + rowBase + tid] = mm;
        g_s[(size_t)bh * SS + rowBase + tid] = ss;
    }
}

// ===========================================================================
// R10a: V transpose: g_v [b][s][h*64+d] fp32 -> g_vt [bh][d][s] bf16.
// grid (S/64, BH), 256 threads, tile 64(s) x 64(d) through smem.
// ===========================================================================
__global__ __launch_bounds__(256) void vt_kernel()
{
    __shared__ __align__(16) char T[64 * 144];   // [s][d] bf16, 72/row

    const int bh = blockIdx.y;
    const int b  = bh >> 4;
    const int h  = bh & 15;
    const int s0 = blockIdx.x * 64;
    const int tid = threadIdx.x;

#pragma unroll
    for (int l = 0; l < 4; l++) {
        int slot = tid + l * 256;          // 0..1023 = 64 rows x 16 float4
        int r  = slot >> 4;
        int c4 = (slot & 15) << 2;
        float4 v = *(const float4*)&g_v[((size_t)b * SS + s0 + r) * EE + h * DD + c4];
        *(uint32_t*)(T + r * 144 + c4 * 2)     = f32x2_bf(v.x, v.y);
        *(uint32_t*)(T + r * 144 + c4 * 2 + 4) = f32x2_bf(v.z, v.w);
    }
    __syncthreads();

#pragma unroll
    for (int l = 0; l < 2; l++) {
        int unit = tid + l * 256;          // 0..511 = 64 d x 8 s-groups
        int d  = unit & 63;
        int jg = unit >> 6;                // 0..7
        union { uint4 q; __nv_bfloat16 hbuf[8]; } u;
#pragma unroll
        for (int i = 0; i < 8; i++)
            u.hbuf[i] = *(__nv_bfloat16*)(T + (jg * 8 + i) * 144 + d * 2);
        *(uint4*)&g_vt[(size_t)bh * DD * SS + (size_t)d * SS + s0 + jg * 8] = u.q;
    }
}

// ===========================================================================
// R10b: normalize + PV via mma.sync (P hi/lo x V bf16) + feature softmax.
// CTA = 128 rows x 64 d of one (b,h); k = 2048 in 32 chunks of 64.
// 8 warps = 4(M) x 2(N), warp tile 32 x 32. Register-prefetch pipelined.
// Smem: Phi/Plo [128][72]b, VT [64][72]b = 46080 B; Ct [128][69] f32 reuses.
// ===========================================================================
#define NP_PHI 0
#define NP_PLO (128*TROWB)              // 18432
#define NP_VT  (2*128*TROWB)            // 36864
#define NP_SMEM (2*128*TROWB + 64*TROWB) // 46080  (>= Ct 128*69*4 = 35328)

__global__ __launch_bounds__(256, 1) void norm_pv_mma_kernel(float* __restrict__ attn)
{
    extern __shared__ __align__(16) char smem[];
    __shared__ float m_s[128];
    __shared__ float i_s[128];

    const int bh = blockIdx.y;
    const int b  = bh >> 4;
    const int h  = bh & 15;
    const int rowBase = blockIdx.x * 128;
    float* __restrict__ P = attn + (size_t)bh * SS * SS;
    const __nv_bfloat16* __restrict__ VT = g_vt + (size_t)bh * DD * SS;

    const int tid  = threadIdx.x;
    const int wid  = tid >> 5;
    const int lane = tid & 31;
    const int g    = lane >> 2;
    const int tig  = lane & 3;
    const int warpM = wid & 3;
    const int warpN = wid >> 2;

    if (tid < 128) {
        m_s[tid] = g_m[(size_t)bh * SS + rowBase + tid];
        i_s[tid] = 1.f / g_s[(size_t)bh * SS + rowBase + tid];
    }
    __syncthreads();

    float acc[2][4][4];
#pragma unroll
    for (int mt = 0; mt < 2; mt++)
#pragma unroll
        for (int nt = 0; nt < 4; nt++)
#pragma unroll
            for (int f = 0; f < 4; f++) acc[mt][nt][f] = 0.f;

    float4 pfp[8];                       // P chunk: 128 rows x 16 floats
    uint4  pfv[2];                       // V^T chunk: 64 d x 64 k bf16
#pragma unroll
    for (int l = 0; l < 8; l++) {
        int slot = tid + l * 256;        // 0..2047 = 128 x 16 float4
        int r  = slot >> 4;
        int c4 = (slot & 15) << 2;       // 0..60
        pfp[l] = *(const float4*)&P[(size_t)(rowBase + r) * SS + c4];
    }
#pragma unroll
    for (int l = 0; l < 2; l++) {
        int vs = tid + l * 256;          // 0..511 = 64 d x 8 groups of 8 bf16
        int d  = vs >> 3;
        int cg = (vs & 7) << 3;
        pfv[l] = *(const uint4*)&VT[(size_t)d * SS + cg];
    }

    for (int ck = 0; ck < 32; ck++) {
        const int k0g = ck * 64;
        // --- store staged P (normalize + writeback + hi/lo split) ---
#pragma unroll
        for (int l = 0; l < 8; l++) {
            int slot = tid + l * 256;
            int r  = slot >> 4;
            int c4 = (slot & 15) << 2;
            float m = m_s[r], inv = i_s[r];
            float4 pv = pfp[l];
            pv.x = __expf(pv.x - m) * inv;
            pv.y = __expf(pv.y - m) * inv;
            pv.z = __expf(pv.z - m) * inv;
            pv.w = __expf(pv.w - m) * inv;
            *(float4*)&P[(size_t)(rowBase + r) * SS + k0g + c4] = pv;
            uint32_t h0, l0, h1, l1;
            f32x2_hilo(pv.x, pv.y, h0, l0);
            f32x2_hilo(pv.z, pv.w, h1, l1);
            uint32_t so = (uint32_t)(r * TROWB + c4 * 2);
            *(uint32_t*)(smem + NP_PHI + so)     = h0;
            *(uint32_t*)(smem + NP_PHI + so + 4) = h1;
            *(uint32_t*)(smem + NP_PLO + so)     = l0;
            *(uint32_t*)(smem + NP_PLO + so + 4) = l1;
        }
        // --- store staged V^T (already bf16, contiguous rows) ---
#pragma unroll
        for (int l = 0; l < 2; l++) {
            int vs = tid + l * 256;
            int d  = vs >> 3;
            int cg = (vs & 7) << 3;
            *(uint4*)(smem + NP_VT + d * TROWB + cg * 2) = pfv[l];
        }
        __syncthreads();

        // --- prefetch next chunk ---
        if (ck < 31) {
            const int kn = (ck + 1) * 64;
#pragma unroll
            for (int l = 0; l < 8; l++) {
                int slot = tid + l * 256;
                int r  = slot >> 4;
                int c4 = (slot & 15) << 2;
                pfp[l] = *(const float4*)&P[(size_t)(rowBase + r) * SS + kn + c4];
            }
#pragma unroll
            for (int l = 0; l < 2; l++) {
                int vs = tid + l * 256;
                int d  = vs >> 3;
                int cg = (vs & 7) << 3;
                pfv[l] = *(const uint4*)&VT[(size_t)d * SS + kn + cg];
            }
        }

        // --- PV mma: 4 k-steps of 16 ---
#pragma unroll
        for (int ks = 0; ks < 4; ks++) {
            const int k0 = ks * 16 + tig * 2;
            uint32_t ah[2][4], al[2][4];
#pragma unroll
            for (int mt = 0; mt < 2; mt++) {
                int r0 = warpM * 32 + mt * 16 + g;
                uint32_t o00 = (uint32_t)(r0 * TROWB + k0 * 2);
                uint32_t o10 = o00 + 8 * TROWB;
                ah[mt][0] = *(const uint32_t*)(smem + NP_PHI + o00);
                ah[mt][1] = *(const uint32_t*)(smem + NP_PHI + o10);
                ah[mt][2] = *(const uint32_t*)(smem + NP_PHI + o00 + 16);
                ah[mt][3] = *(const uint32_t*)(smem + NP_PHI + o10 + 16);
                al[mt][0] = *(const uint32_t*)(smem + NP_PLO + o00);
                al[mt][1] = *(const uint32_t*)(smem + NP_PLO + o10);
                al[mt][2] = *(const uint32_t*)(smem + NP_PLO + o00 + 16);
                al[mt][3] = *(const uint32_t*)(smem + NP_PLO + o10 + 16);
            }
#pragma unroll
            for (int nt = 0; nt < 4; nt++) {
                int c0 = warpN * 32 + nt * 8 + g;     // d column
                uint32_t ob = (uint32_t)(c0 * TROWB + k0 * 2);
                uint32_t b0 = *(const uint32_t*)(smem + NP_VT + ob);
                uint32_t b1 = *(const uint32_t*)(smem + NP_VT + ob + 16);
#pragma unroll
                for (int mt = 0; mt < 2; mt++) {
                    mma_bf16(acc[mt][nt], ah[mt][0], ah[mt][1], ah[mt][2], ah[mt][3], b0, b1);
                    mma_bf16(acc[mt][nt], al[mt][0], al[mt][1], al[mt][2], al[mt][3], b0, b1);
                }
            }
        }
        __syncthreads();
    }

    // --- epilogue: acc -> Ct (reuse staging smem), feature softmax ---
    float* Ct = (float*)smem;            // [128][69]
#pragma unroll
    for (int mt = 0; mt < 2; mt++)
#pragma unroll
        for (int nt = 0; nt < 4; nt++) {
            int r0 = warpM * 32 + mt * 16 + g;
            int c0 = warpN * 32 + nt * 8 + tig * 2;
            Ct[r0 * 69 + c0]           = acc[mt][nt][0];
            Ct[r0 * 69 + c0 + 1]       = acc[mt][nt][1];
            Ct[(r0 + 8) * 69 + c0]     = acc[mt][nt][2];
            Ct[(r0 + 8) * 69 + c0 + 1] = acc[mt][nt][3];
        }
    __syncthreads();

    if (tid < 128) {
        const int r = tid;
        float* rp = Ct + r * 69;
        float m = rp[0];
#pragma unroll
        for (int d = 1; d < DD; d++) m = fmaxf(m, rp[d]);
        float s = 0.f;
#pragma unroll
        for (int d = 0; d < DD; d++) { float e = __expf(rp[d] - m); rp[d] = e; s += e; }
        float inv = 1.f / s;
        float* __restrict__ dst = g_ctx + ((size_t)b * SS + rowBase + r) * EE + h * DD;
#pragma unroll
        for (int d = 0; d < DD; d++) dst[d] = rp[d] * inv;
    }
}

// ---------------------------------------------------------------------------
extern "C" void kernel_launch(void* const* d_in, const int* in_sizes, int n_in,
                              void* d_out, int out_size)
{
    const float* key   = (const float*)d_in[0];
    const float* query = (const float*)d_in[1];
    const float* value = (const float*)d_in[2];
    const float* wk_w  = (const float*)d_in[3];
    const float* wk_b  = (const float*)d_in[4];
    const float* wq_w  = (const float*)d_in[5];
    const float* wq_b  = (const float*)d_in[6];
    const float* wv_w  = (const float*)d_in[7];
    const float* wv_b  = (const float*)d_in[8];
    const float* out_w = (const float*)d_in[9];
    const float* out_b = (const float*)d_in[10];

    float* out  = (float*)d_out;                       // [B,S,E]
    float* attn = out + (size_t)MTOT * EE;             // [B,H,S,S]

    static int smem_set = 0;
    if (!smem_set) {
        cudaFuncSetAttribute(gemm_mma_kernel,
                             cudaFuncAttributeMaxDynamicSharedMemorySize, GEMM_SMEM);
        cudaFuncSetAttribute(scores_mma_kernel,
                             cudaFuncAttributeMaxDynamicSharedMemorySize, SC_SMEM);
        cudaFuncSetAttribute(norm_pv_mma_kernel,
                             cudaFuncAttributeMaxDynamicSharedMemorySize, NP_SMEM);
        smem_set = 1;
    }

    dim3 gProj(EE / 128, MTOT / 128);                  // (8, 64)
    gemm_mma_kernel<<<gProj, 256, GEMM_SMEM>>>(query, 0, wq_w, wq_b, nullptr, 0);
    gemm_mma_kernel<<<gProj, 256, GEMM_SMEM>>>(key,   0, wk_w, wk_b, nullptr, 1);
    gemm_mma_kernel<<<gProj, 256, GEMM_SMEM>>>(value, 0, wv_w, wv_b, nullptr, 2);

    dim3 gVT(SS / 64, BH);                             // (32, 64)
    vt_kernel<<<gVT, 256>>>();

    dim3 gScores(SS / 128, BH);                        // (16, 64)
    scores_mma_kernel<<<gScores, 256, SC_SMEM>>>(attn);

    dim3 gPV(SS / 128, BH);                            // (16, 64)
    norm_pv_mma_kernel<<<gPV, 256, NP_SMEM>>>(attn);

    gemm_mma_kernel<<<gProj, 256, GEMM_SMEM>>>(nullptr, 1, out_w, out_b, out, 3);
}

// round 11
// speedup vs baseline: 1.6065x; 1.0136x over previous
#include <cuda_runtime.h>
#include <cuda_bf16.h>
#include <math.h>
#include <stdint.h>

// MultiHeadAttention: B=4, S=2048, E=1024, H=16, D=64
// Outputs: out [B,S,E] fp32, attention_weights [B,H,S,S] fp32.
//
// R11: fragment loads in all mma kernels converted from scalar LDS.32 to
// ldmatrix (LDSM) -- 192 LDS -> 80 LDSM per chunk per warp, attacking the
// issue-bound bottleneck (tensor=39%, issue=32% at occ 12.5%).
// Staging/pipelining/numerics unchanged from R10 pass (1844.9us).

#define BB   4
#define SS   2048
#define EE   1024
#define HH   16
#define DD   64
#define MTOT (BB*SS)          // 8192
#define BH   (BB*HH)          // 64

__device__ float g_q[MTOT*EE];
__device__ float g_k[MTOT*EE];
__device__ float g_v[MTOT*EE];
__device__ float g_ctx[MTOT*EE];
__device__ float g_m[BH*SS];
__device__ float g_s[BH*SS];
__device__ __nv_bfloat16 g_vt[(size_t)BH*DD*SS];   // V^T per head: [bh][d][s]

// ===========================================================================
// helpers
// ===========================================================================
__device__ __forceinline__ uint32_t smem_u32(const void* p) {
    uint32_t a;
    asm("{ .reg .u64 t; cvta.to.shared.u64 t, %1; cvt.u32.u64 %0, t; }"
        : "=r"(a) : "l"(p));
    return a;
}
__device__ __forceinline__ void f32x2_hilo(float x, float y, uint32_t& hi, uint32_t& lo) {
    __nv_bfloat162 h, l;
    h.x = __float2bfloat16(x); l.x = __float2bfloat16(x - __bfloat162float(h.x));
    h.y = __float2bfloat16(y); l.y = __float2bfloat16(y - __bfloat162float(h.y));
    hi = *(uint32_t*)&h; lo = *(uint32_t*)&l;
}
__device__ __forceinline__ uint32_t f32x2_bf(float x, float y) {
    __nv_bfloat162 h;
    h.x = __float2bfloat16(x); h.y = __float2bfloat16(y);
    return *(uint32_t*)&h;
}
__device__ __forceinline__ void mma_bf16(float* d,
    uint32_t a0, uint32_t a1, uint32_t a2, uint32_t a3, uint32_t b0, uint32_t b1)
{
    asm volatile(
        "mma.sync.aligned.m16n8k16.row.col.f32.bf16.bf16.f32 "
        "{%0,%1,%2,%3}, {%4,%5,%6,%7}, {%8,%9}, {%0,%1,%2,%3};"
        : "+f"(d[0]), "+f"(d[1]), "+f"(d[2]), "+f"(d[3])
        : "r"(a0), "r"(a1), "r"(a2), "r"(a3), "r"(b0), "r"(b1));
}
__device__ __forceinline__ void ldsm_x4(uint32_t* r, uint32_t addr) {
    asm volatile("ldmatrix.sync.aligned.m8n8.x4.shared.b16 {%0,%1,%2,%3}, [%4];"
        : "=r"(r[0]), "=r"(r[1]), "=r"(r[2]), "=r"(r[3]) : "r"(addr));
}
__device__ __forceinline__ void ldsm_x2(uint32_t& r0, uint32_t& r1, uint32_t addr) {
    asm volatile("ldmatrix.sync.aligned.m8n8.x2.shared.b16 {%0,%1}, [%2];"
        : "=r"(r0), "=r"(r1) : "r"(addr));
}

#define TPAD   72                       // bf16 elems per smem row (64 + 8 pad)
#define TROWB  (TPAD*2)                 // 144 bytes

// A-fragment ldmatrix lane offset: lanes 0-15 -> rows 0-15 @k0; 16-31 -> rows @k0+8
#define AOFF(lane) ((uint32_t)(((lane) & 15) * TROWB + ((lane) >> 4) * 16))
// B-fragment (x2) lane offset: lanes 0-7 -> n rows @k0; 8-15 -> @k0+8
#define BOFF(lane) ((uint32_t)(((lane) & 7) * TROWB + (((lane) >> 3) & 1) * 16))

// ===========================================================================
// Tensor-core projection GEMM, pipelined staging + LDSM fragments.
// ===========================================================================
#define OFF_AHI 0
#define OFF_ALO (128*TROWB)
#define OFF_BHI (2*128*TROWB)
#define OFF_BLO (3*128*TROWB)
#define GEMM_SMEM (4*128*TROWB)         // 73728

__global__ __launch_bounds__(256, 1) void gemm_mma_kernel(
    const float* __restrict__ A_ext, int a_sel,
    const float* __restrict__ W, const float* __restrict__ bias,
    float* __restrict__ C_ext, int c_sel)
{
    extern __shared__ __align__(16) char smem[];
    const uint32_t sb = smem_u32(smem);

    const float* __restrict__ A = (a_sel == 0) ? A_ext : g_ctx;
    float* __restrict__ C;
    switch (c_sel) {
        case 0:  C = g_q;   break;
        case 1:  C = g_k;   break;
        case 2:  C = g_v;   break;
        default: C = C_ext; break;
    }

    const int tid  = threadIdx.x;
    const int wid  = tid >> 5;
    const int lane = tid & 31;
    const int g    = lane >> 2;
    const int tig  = lane & 3;
    const int warpM = wid & 3;
    const int warpN = wid >> 2;
    const int rowBase = blockIdx.y * 128;
    const int colBase = blockIdx.x * 128;

    // ldmatrix base addresses
    uint32_t aHi[2], aLo[2], bHi[8], bLo[8];
#pragma unroll
    for (int mt = 0; mt < 2; mt++) {
        uint32_t r0 = (uint32_t)((warpM * 32 + mt * 16) * TROWB) + AOFF(lane);
        aHi[mt] = sb + OFF_AHI + r0;
        aLo[mt] = sb + OFF_ALO + r0;
    }
#pragma unroll
    for (int nt = 0; nt < 8; nt++) {
        uint32_t c0 = (uint32_t)((warpN * 64 + nt * 8) * TROWB) + BOFF(lane);
        bHi[nt] = sb + OFF_BHI + c0;
        bLo[nt] = sb + OFF_BLO + c0;
    }

    float acc[2][8][4];
#pragma unroll
    for (int mt = 0; mt < 2; mt++)
#pragma unroll
        for (int nt = 0; nt < 8; nt++)
#pragma unroll
            for (int f = 0; f < 4; f++) acc[mt][nt][f] = 0.f;

    float4 pfa[8], pfb[8];
#pragma unroll
    for (int l = 0; l < 8; l++) {
        int slot = tid + l * 256;
        int r  = slot >> 4;
        int c4 = (slot & 15) << 2;
        pfa[l] = *(const float4*)&A[(size_t)(rowBase + r) * EE + c4];
        pfb[l] = *(const float4*)&W[(size_t)(colBase + r) * EE + c4];
    }

    for (int kc = 0; kc < 16; kc++) {
#pragma unroll
        for (int l = 0; l < 8; l++) {
            int slot = tid + l * 256;
            int r  = slot >> 4;
            int c4 = (slot & 15) << 2;
            uint32_t so = (uint32_t)(r * TROWB + c4 * 2);
            uint32_t h0, l0, h1, l1;
            f32x2_hilo(pfa[l].x, pfa[l].y, h0, l0);
            f32x2_hilo(pfa[l].z, pfa[l].w, h1, l1);
            *(uint32_t*)(smem + OFF_AHI + so)     = h0;
            *(uint32_t*)(smem + OFF_AHI + so + 4) = h1;
            *(uint32_t*)(smem + OFF_ALO + so)     = l0;
            *(uint32_t*)(smem + OFF_ALO + so + 4) = l1;
            f32x2_hilo(pfb[l].x, pfb[l].y, h0, l0);
            f32x2_hilo(pfb[l].z, pfb[l].w, h1, l1);
            *(uint32_t*)(smem + OFF_BHI + so)     = h0;
            *(uint32_t*)(smem + OFF_BHI + so + 4) = h1;
            *(uint32_t*)(smem + OFF_BLO + so)     = l0;
            *(uint32_t*)(smem + OFF_BLO + so + 4) = l1;
        }
        __syncthreads();

        if (kc < 15) {
            const int k0g = (kc + 1) * 64;
#pragma unroll
            for (int l = 0; l < 8; l++) {
                int slot = tid + l * 256;
                int r  = slot >> 4;
                int c4 = (slot & 15) << 2;
                pfa[l] = *(const float4*)&A[(size_t)(rowBase + r) * EE + k0g + c4];
                pfb[l] = *(const float4*)&W[(size_t)(colBase + r) * EE + k0g + c4];
            }
        }

#pragma unroll
        for (int ks = 0; ks < 4; ks++) {
            const uint32_t kb = (uint32_t)(ks * 32);
            uint32_t ah[2][4], al[2][4];
#pragma unroll
            for (int mt = 0; mt < 2; mt++) {
                ldsm_x4(ah[mt], aHi[mt] + kb);
                ldsm_x4(al[mt], aLo[mt] + kb);
            }
#pragma unroll
            for (int nt = 0; nt < 8; nt++) {
                uint32_t bh0, bh1, bl0, bl1;
                ldsm_x2(bh0, bh1, bHi[nt] + kb);
                ldsm_x2(bl0, bl1, bLo[nt] + kb);
#pragma unroll
                for (int mt = 0; mt < 2; mt++) {
                    mma_bf16(acc[mt][nt], ah[mt][0], ah[mt][1], ah[mt][2], ah[mt][3], bh0, bh1);
                    mma_bf16(acc[mt][nt], ah[mt][0], ah[mt][1], ah[mt][2], ah[mt][3], bl0, bl1);
                    mma_bf16(acc[mt][nt], al[mt][0], al[mt][1], al[mt][2], al[mt][3], bh0, bh1);
                }
            }
        }
        __syncthreads();
    }

#pragma unroll
    for (int nt = 0; nt < 8; nt++) {
        int col = colBase + warpN * 64 + nt * 8 + tig * 2;
        float b0 = bias[col], b1 = bias[col + 1];
#pragma unroll
        for (int mt = 0; mt < 2; mt++) {
            int row0 = rowBase + warpM * 32 + mt * 16 + g;
            float2 v0 = make_float2(acc[mt][nt][0] + b0, acc[mt][nt][1] + b1);
            float2 v1 = make_float2(acc[mt][nt][2] + b0, acc[mt][nt][3] + b1);
            *(float2*)&C[(size_t)row0 * EE + col]       = v0;
            *(float2*)&C[(size_t)(row0 + 8) * EE + col] = v1;
        }
    }
}

// ===========================================================================
// scores + online row stats, pipelined + LDSM fragments.
// ===========================================================================
#define SC_QHI 0
#define SC_QLO (128*TROWB)
#define SC_KHI (2*128*TROWB)
#define SC_KLO (3*128*TROWB)
#define SC_SMEM (4*128*TROWB)           // 73728

__global__ __launch_bounds__(256, 1) void scores_mma_kernel(float* __restrict__ attn)
{
    extern __shared__ __align__(16) char smem[];
    __shared__ float sm_m[2][128];
    __shared__ float sm_s[2][128];
    const uint32_t sb = smem_u32(smem);

    const int bh = blockIdx.y;
    const int b  = bh >> 4;
    const int h  = bh & 15;
    const int rowBase = blockIdx.x * 128;
    const float* __restrict__ Qp = g_q + (size_t)b * SS * EE + h * DD;
    const float* __restrict__ Kp = g_k + (size_t)b * SS * EE + h * DD;
    float* __restrict__ Cb = attn + (size_t)bh * SS * SS;

    const int tid  = threadIdx.x;
    const int wid  = tid >> 5;
    const int lane = tid & 31;
    const int g    = lane >> 2;
    const int tig  = lane & 3;
    const int warpM = wid & 3;
    const int warpN = wid >> 2;

    uint32_t aHi[2], aLo[2], bHi[8], bLo[8];
#pragma unroll
    for (int mt = 0; mt < 2; mt++) {
        uint32_t r0 = (uint32_t)((warpM * 32 + mt * 16) * TROWB) + AOFF(lane);
        aHi[mt] = sb + SC_QHI + r0;
        aLo[mt] = sb + SC_QLO + r0;
    }
#pragma unroll
    for (int nt = 0; nt < 8; nt++) {
        uint32_t c0 = (uint32_t)((warpN * 64 + nt * 8) * TROWB) + BOFF(lane);
        bHi[nt] = sb + SC_KHI + c0;
        bLo[nt] = sb + SC_KLO + c0;
    }

#pragma unroll
    for (int l = 0; l < 8; l++) {
        int id = tid + l * 256;
        int r  = id >> 4;
        int c4 = (id & 15) << 2;
        uint32_t so = (uint32_t)(r * TROWB + c4 * 2);
        float4 v = *(const float4*)&Qp[(size_t)(rowBase + r) * EE + c4];
        uint32_t h0, l0, h1, l1;
        f32x2_hilo(v.x, v.y, h0, l0);
        f32x2_hilo(v.z, v.w, h1, l1);
        *(uint32_t*)(smem + SC_QHI + so)     = h0;
        *(uint32_t*)(smem + SC_QHI + so + 4) = h1;
        *(uint32_t*)(smem + SC_QLO + so)     = l0;
        *(uint32_t*)(smem + SC_QLO + so + 4) = l1;
    }

    float m_run[4], s_run[4];
#pragma unroll
    for (int i = 0; i < 4; i++) { m_run[i] = -INFINITY; s_run[i] = 0.f; }

    float4 pfk[8];
#pragma unroll
    for (int l = 0; l < 8; l++) {
        int id = tid + l * 256;
        int r  = id >> 4;
        int c4 = (id & 15) << 2;
        pfk[l] = *(const float4*)&Kp[(size_t)r * EE + c4];
    }

    for (int ct = 0; ct < 16; ct++) {
        const int colBase = ct * 128;
#pragma unroll
        for (int l = 0; l < 8; l++) {
            int id = tid + l * 256;
            int r  = id >> 4;
            int c4 = (id & 15) << 2;
            uint32_t so = (uint32_t)(r * TROWB + c4 * 2);
            uint32_t h0, l0, h1, l1;
            f32x2_hilo(pfk[l].x, pfk[l].y, h0, l0);
            f32x2_hilo(pfk[l].z, pfk[l].w, h1, l1);
            *(uint32_t*)(smem + SC_KHI + so)     = h0;
            *(uint32_t*)(smem + SC_KHI + so + 4) = h1;
            *(uint32_t*)(smem + SC_KLO + so)     = l0;
            *(uint32_t*)(smem + SC_KLO + so + 4) = l1;
        }
        __syncthreads();

        if (ct < 15) {
            const int nb = (ct + 1) * 128;
#pragma unroll
            for (int l = 0; l < 8; l++) {
                int id = tid + l * 256;
                int r  = id >> 4;
                int c4 = (id & 15) << 2;
                pfk[l] = *(const float4*)&Kp[(size_t)(nb + r) * EE + c4];
            }
        }

        float acc[2][8][4];
#pragma unroll
        for (int mt = 0; mt < 2; mt++)
#pragma unroll
            for (int nt = 0; nt < 8; nt++)
#pragma unroll
                for (int f = 0; f < 4; f++) acc[mt][nt][f] = 0.f;

#pragma unroll
        for (int ks = 0; ks < 4; ks++) {
            const uint32_t kb = (uint32_t)(ks * 32);
            uint32_t ah[2][4], al[2][4];
#pragma unroll
            for (int mt = 0; mt < 2; mt++) {
                ldsm_x4(ah[mt], aHi[mt] + kb);
                ldsm_x4(al[mt], aLo[mt] + kb);
            }
#pragma unroll
            for (int nt = 0; nt < 8; nt++) {
                uint32_t bh0, bh1, bl0, bl1;
                ldsm_x2(bh0, bh1, bHi[nt] + kb);
                ldsm_x2(bl0, bl1, bLo[nt] + kb);
#pragma unroll
                for (int mt = 0; mt < 2; mt++) {
                    mma_bf16(acc[mt][nt], ah[mt][0], ah[mt][1], ah[mt][2], ah[mt][3], bh0, bh1);
                    mma_bf16(acc[mt][nt], ah[mt][0], ah[mt][1], ah[mt][2], ah[mt][3], bl0, bl1);
                    mma_bf16(acc[mt][nt], al[mt][0], al[mt][1], al[mt][2], al[mt][3], bh0, bh1);
                }
            }
        }

#pragma unroll
        for (int mt = 0; mt < 2; mt++) {
#pragma unroll
            for (int nt = 0; nt < 8; nt++) {
#pragma unroll
                for (int f = 0; f < 4; f++) acc[mt][nt][f] *= 0.125f;
                int col  = colBase + warpN * 64 + nt * 8 + tig * 2;
                int row0 = rowBase + warpM * 32 + mt * 16 + g;
                *(float2*)&Cb[(size_t)row0 * SS + col] =
                    make_float2(acc[mt][nt][0], acc[mt][nt][1]);
                *(float2*)&Cb[(size_t)(row0 + 8) * SS + col] =
                    make_float2(acc[mt][nt][2], acc[mt][nt][3]);
            }
#pragma unroll
            for (int p = 0; p < 2; p++) {
                int si = mt * 2 + p;
                float rmax = -INFINITY;
#pragma unroll
                for (int nt = 0; nt < 8; nt++) {
                    rmax = fmaxf(rmax, fmaxf(acc[mt][nt][p * 2], acc[mt][nt][p * 2 + 1]));
                }
                rmax = fmaxf(rmax, __shfl_xor_sync(0xffffffffu, rmax, 1));
                rmax = fmaxf(rmax, __shfl_xor_sync(0xffffffffu, rmax, 2));
                float m_new = fmaxf(m_run[si], rmax);
                float psum = 0.f;
#pragma unroll
                for (int nt = 0; nt < 8; nt++) {
                    psum += __expf(acc[mt][nt][p * 2]     - m_new);
                    psum += __expf(acc[mt][nt][p * 2 + 1] - m_new);
                }
                psum += __shfl_xor_sync(0xffffffffu, psum, 1);
                psum += __shfl_xor_sync(0xffffffffu, psum, 2);
                s_run[si] = s_run[si] * __expf(m_run[si] - m_new) + psum;
                m_run[si] = m_new;
            }
        }
        __syncthreads();
    }

    if (tig == 0) {
#pragma unroll
        for (int mt = 0; mt < 2; mt++)
#pragma unroll
            for (int p = 0; p < 2; p++) {
                int r = warpM * 32 + mt * 16 + p * 8 + g;
                sm_m[warpN][r] = m_run[mt * 2 + p];
                sm_s[warpN][r] = s_run[mt * 2 + p];
            }
    }
    __syncthreads();
    if (tid < 128) {
        float m0 = sm_m[0][tid], m1 = sm_m[1][tid];
        float mm = fmaxf(m0, m1);
        float ss = sm_s[0][tid] * __expf(m0 - mm) + sm_s[1][tid] * __expf(m1 - mm);
        g_m[(size_t)bh * SS + rowBase + tid] = mm;
        g_s[(size_t)bh * SS + rowBase + tid] = ss;
    }
}

// ===========================================================================
// V transpose (unchanged from R10 pass @13.8us).
// ===========================================================================
__global__ __launch_bounds__(256) void vt_kernel()
{
    __shared__ __align__(16) char T[64 * 144];

    const int bh = blockIdx.y;
    const int b  = bh >> 4;
    const int h  = bh & 15;
    const int s0 = blockIdx.x * 64;
    const int tid = threadIdx.x;

#pragma unroll
    for (int l = 0; l < 4; l++) {
        int slot = tid + l * 256;
        int r  = slot >> 4;
        int c4 = (slot & 15) << 2;
        float4 v = *(const float4*)&g_v[((size_t)b * SS + s0 + r) * EE + h * DD + c4];
        *(uint32_t*)(T + r * 144 + c4 * 2)     = f32x2_bf(v.x, v.y);
        *(uint32_t*)(T + r * 144 + c4 * 2 + 4) = f32x2_bf(v.z, v.w);
    }
    __syncthreads();

#pragma unroll
    for (int l = 0; l < 2; l++) {
        int unit = tid + l * 256;
        int d  = unit & 63;
        int jg = unit >> 6;
        union { uint4 q; __nv_bfloat16 hbuf[8]; } u;
#pragma unroll
        for (int i = 0; i < 8; i++)
            u.hbuf[i] = *(__nv_bfloat16*)(T + (jg * 8 + i) * 144 + d * 2);
        *(uint4*)&g_vt[(size_t)bh * DD * SS + (size_t)d * SS + s0 + jg * 8] = u.q;
    }
}

// ===========================================================================
// normalize + PV (P hi/lo x V bf16) + feature softmax, LDSM fragments.
// ===========================================================================
#define NP_PHI 0
#define NP_PLO (128*TROWB)
#define NP_VT  (2*128*TROWB)
#define NP_SMEM (2*128*TROWB + 64*TROWB) // 46080

__global__ __launch_bounds__(256, 1) void norm_pv_mma_kernel(float* __restrict__ attn)
{
    extern __shared__ __align__(16) char smem[];
    __shared__ float m_s[128];
    __shared__ float i_s[128];
    const uint32_t sb = smem_u32(smem);

    const int bh = blockIdx.y;
    const int b  = bh >> 4;
    const int h  = bh & 15;
    const int rowBase = blockIdx.x * 128;
    float* __restrict__ P = attn + (size_t)bh * SS * SS;
    const __nv_bfloat16* __restrict__ VT = g_vt + (size_t)bh * DD * SS;

    const int tid  = threadIdx.x;
    const int wid  = tid >> 5;
    const int lane = tid & 31;
    const int g    = lane >> 2;
    const int tig  = lane & 3;
    const int warpM = wid & 3;
    const int warpN = wid >> 2;

    uint32_t aHi[2], aLo[2], bVT[4];
#pragma unroll
    for (int mt = 0; mt < 2; mt++) {
        uint32_t r0 = (uint32_t)((warpM * 32 + mt * 16) * TROWB) + AOFF(lane);
        aHi[mt] = sb + NP_PHI + r0;
        aLo[mt] = sb + NP_PLO + r0;
    }
#pragma unroll
    for (int nt = 0; nt < 4; nt++) {
        bVT[nt] = sb + NP_VT + (uint32_t)((warpN * 32 + nt * 8) * TROWB) + BOFF(lane);
    }

    if (tid < 128) {
        m_s[tid] = g_m[(size_t)bh * SS + rowBase + tid];
        i_s[tid] = 1.f / g_s[(size_t)bh * SS + rowBase + tid];
    }
    __syncthreads();

    float acc[2][4][4];
#pragma unroll
    for (int mt = 0; mt < 2; mt++)
#pragma unroll
        for (int nt = 0; nt < 4; nt++)
#pragma unroll
            for (int f = 0; f < 4; f++) acc[mt][nt][f] = 0.f;

    float4 pfp[8];
    uint4  pfv[2];
#pragma unroll
    for (int l = 0; l < 8; l++) {
        int slot = tid + l * 256;
        int r  = slot >> 4;
        int c4 = (slot & 15) << 2;
        pfp[l] = *(const float4*)&P[(size_t)(rowBase + r) * SS + c4];
    }
#pragma unroll
    for (int l = 0; l < 2; l++) {
        int vs = tid + l * 256;
        int d  = vs >> 3;
        int cg = (vs & 7) << 3;
        pfv[l] = *(const uint4*)&VT[(size_t)d * SS + cg];
    }

    for (int ck = 0; ck < 32; ck++) {
        const int k0g = ck * 64;
#pragma unroll
        for (int l = 0; l < 8; l++) {
            int slot = tid + l * 256;
            int r  = slot >> 4;
            int c4 = (slot & 15) << 2;
            float m = m_s[r], inv = i_s[r];
            float4 pv = pfp[l];
            pv.x = __expf(pv.x - m) * inv;
            pv.y = __expf(pv.y - m) * inv;
            pv.z = __expf(pv.z - m) * inv;
            pv.w = __expf(pv.w - m) * inv;
            *(float4*)&P[(size_t)(rowBase + r) * SS + k0g + c4] = pv;
            uint32_t h0, l0, h1, l1;
            f32x2_hilo(pv.x, pv.y, h0, l0);
            f32x2_hilo(pv.z, pv.w, h1, l1);
            uint32_t so = (uint32_t)(r * TROWB + c4 * 2);
            *(uint32_t*)(smem + NP_PHI + so)     = h0;
            *(uint32_t*)(smem + NP_PHI + so + 4) = h1;
            *(uint32_t*)(smem + NP_PLO + so)     = l0;
            *(uint32_t*)(smem + NP_PLO + so + 4) = l1;
        }
#pragma unroll
        for (int l = 0; l < 2; l++) {
            int vs = tid + l * 256;
            int d  = vs >> 3;
            int cg = (vs & 7) << 3;
            *(uint4*)(smem + NP_VT + d * TROWB + cg * 2) = pfv[l];
        }
        __syncthreads();

        if (ck < 31) {
            const int kn = (ck + 1) * 64;
#pragma unroll
            for (int l = 0; l < 8; l++) {
                int slot = tid + l * 256;
                int r  = slot >> 4;
                int c4 = (slot & 15) << 2;
                pfp[l] = *(const float4*)&P[(size_t)(rowBase + r) * SS + kn + c4];
            }
#pragma unroll
            for (int l = 0; l < 2; l++) {
                int vs = tid + l * 256;
                int d  = vs >> 3;
                int cg = (vs & 7) << 3;
                pfv[l] = *(const uint4*)&VT[(size_t)d * SS + kn + cg];
            }
        }

#pragma unroll
        for (int ks = 0; ks < 4; ks++) {
            const uint32_t kb = (uint32_t)(ks * 32);
            uint32_t ah[2][4], al[2][4];
#pragma unroll
            for (int mt = 0; mt < 2; mt++) {
                ldsm_x4(ah[mt], aHi[mt] + kb);
                ldsm_x4(al[mt], aLo[mt] + kb);
            }
#pragma unroll
            for (int nt = 0; nt < 4; nt++) {
                uint32_t b0, b1;
                ldsm_x2(b0, b1, bVT[nt] + kb);
#pragma unroll
                for (int mt = 0; mt < 2; mt++) {
                    mma_bf16(acc[mt][nt], ah[mt][0], ah[mt][1], ah[mt][2], ah[mt][3], b0, b1);
                    mma_bf16(acc[mt][nt], al[mt][0], al[mt][1], al[mt][2], al[mt][3], b0, b1);
                }
            }
        }
        __syncthreads();
    }

    float* Ct = (float*)smem;            // [128][69]
#pragma unroll
    for (int mt = 0; mt < 2; mt++)
#pragma unroll
        for (int nt = 0; nt < 4; nt++) {
            int r0 = warpM * 32 + mt * 16 + g;
            int c0 = warpN * 32 + nt * 8 + tig * 2;
            Ct[r0 * 69 + c0]           = acc[mt][nt][0];
            Ct[r0 * 69 + c0 + 1]       = acc[mt][nt][1];
            Ct[(r0 + 8) * 69 + c0]     = acc[mt][nt][2];
            Ct[(r0 + 8) * 69 + c0 + 1] = acc[mt][nt][3];
        }
    __syncthreads();

    if (tid < 128) {
        const int r = tid;
        float* rp = Ct + r * 69;
        float m = rp[0];
#pragma unroll
        for (int d = 1; d < DD; d++) m = fmaxf(m, rp[d]);
        float s = 0.f;
#pragma unroll
        for (int d = 0; d < DD; d++) { float e = __expf(rp[d] - m); rp[d] = e; s += e; }
        float inv = 1.f / s;
        float* __restrict__ dst = g_ctx + ((size_t)b * SS + rowBase + r) * EE + h * DD;
#pragma unroll
        for (int d = 0; d < DD; d++) dst[d] = rp[d] * inv;
    }
}

// ---------------------------------------------------------------------------
extern "C" void kernel_launch(void* const* d_in, const int* in_sizes, int n_in,
                              void* d_out, int out_size)
{
    const float* key   = (const float*)d_in[0];
    const float* query = (const float*)d_in[1];
    const float* value = (const float*)d_in[2];
    const float* wk_w  = (const float*)d_in[3];
    const float* wk_b  = (const float*)d_in[4];
    const float* wq_w  = (const float*)d_in[5];
    const float* wq_b  = (const float*)d_in[6];
    const float* wv_w  = (const float*)d_in[7];
    const float* wv_b  = (const float*)d_in[8];
    const float* out_w = (const float*)d_in[9];
    const float* out_b = (const float*)d_in[10];

    float* out  = (float*)d_out;                       // [B,S,E]
    float* attn = out + (size_t)MTOT * EE;             // [B,H,S,S]

    static int smem_set = 0;
    if (!smem_set) {
        cudaFuncSetAttribute(gemm_mma_kernel,
                             cudaFuncAttributeMaxDynamicSharedMemorySize, GEMM_SMEM);
        cudaFuncSetAttribute(scores_mma_kernel,
                             cudaFuncAttributeMaxDynamicSharedMemorySize, SC_SMEM);
        cudaFuncSetAttribute(norm_pv_mma_kernel,
                             cudaFuncAttributeMaxDynamicSharedMemorySize, NP_SMEM);
        smem_set = 1;
    }

    dim3 gProj(EE / 128, MTOT / 128);                  // (8, 64)
    gemm_mma_kernel<<<gProj, 256, GEMM_SMEM>>>(query, 0, wq_w, wq_b, nullptr, 0);
    gemm_mma_kernel<<<gProj, 256, GEMM_SMEM>>>(key,   0, wk_w, wk_b, nullptr, 1);
    gemm_mma_kernel<<<gProj, 256, GEMM_SMEM>>>(value, 0, wv_w, wv_b, nullptr, 2);

    dim3 gVT(SS / 64, BH);                             // (32, 64)
    vt_kernel<<<gVT, 256>>>();

    dim3 gScores(SS / 128, BH);                        // (16, 64)
    scores_mma_kernel<<<gScores, 256, SC_SMEM>>>(attn);

    dim3 gPV(SS / 128, BH);                            // (16, 64)
    norm_pv_mma_kernel<<<gPV, 256, NP_SMEM>>>(attn);

    gemm_mma_kernel<<<gProj, 256, GEMM_SMEM>>>(nullptr, 1, out_w, out_b, out, 3);
}